// round 6
// baseline (speedup 1.0000x reference)
#include <cuda_runtime.h>
#include <math.h>

// Problem constants
#define BB 2
#define SS 2048
#define DD 1024
#define HH 16
#define DK 64
#define MM (BB*SS)   // 4096 rows

// Scratch (allocation-free rule: __device__ globals)
__device__ float g_q[BB*HH*SS*DK];     // [b,h,s,dk] 16MB
__device__ float g_k[BB*HH*SS*DK];
__device__ float g_v[BB*HH*SS*DK];
__device__ float g_attn[BB*SS*DD];     // [b,s,D]
__device__ float g_cos[SS*(DK/2)];     // [s][32]
__device__ float g_sin[SS*(DK/2)];

// ---------------------------------------------------------------------------
// RoPE table: angles computed in double, sincos in float.
// ---------------------------------------------------------------------------
__global__ void rope_table_kernel() {
    int idx = blockIdx.x * blockDim.x + threadIdx.x;
    if (idx >= SS*(DK/2)) return;
    int s = idx >> 5;
    int j = idx & 31;
    // inv_freq = 10000^(-2j/64); ln(10000) = 9.210340371976184
    double inv = exp(-(double)(2*j) / 64.0 * 9.210340371976184);
    float ang = (float)((double)s * inv);
    g_cos[idx] = cosf(ang);
    g_sin[idx] = sinf(ang);
}

// ---------------------------------------------------------------------------
// SGEMM: C[m][n] = sum_k A[m][k] * W[n][k]   (A: 4096x1024, W: 1024x1024)
// BM=BN=128, BK=16, 256 threads, 8x8 per thread.
// mode 0: plain row-major write (out = [4096][1024])
// mode 1: permuted write to [b,h,s,dk]
// mode 2: RoPE + permuted write
// ---------------------------------------------------------------------------
__global__ __launch_bounds__(256) void gemm_kernel(
    const float* __restrict__ A, const float* __restrict__ W,
    float* __restrict__ out, int mode)
{
    __shared__ __align__(16) float As[16][128];   // k-major
    __shared__ __align__(16) float Bs[16][128];
    const int tid   = threadIdx.x;
    const int mBase = blockIdx.y * 128;
    const int nBase = blockIdx.x * 128;
    const int tr = tid >> 4;         // 0..15
    const int tc = tid & 15;         // 0..15
    const int lRow = tid >> 2;       // 0..63
    const int lK   = (tid & 3) * 4;  // 0,4,8,12

    float acc[8][8];
    #pragma unroll
    for (int i = 0; i < 8; i++)
        #pragma unroll
        for (int j = 0; j < 8; j++) acc[i][j] = 0.f;

    for (int k0 = 0; k0 < 1024; k0 += 16) {
        #pragma unroll
        for (int hh = 0; hh < 2; hh++) {
            int r = lRow + hh*64;
            float4 va = *(const float4*)&A[(mBase + r)*1024 + k0 + lK];
            As[lK+0][r] = va.x; As[lK+1][r] = va.y;
            As[lK+2][r] = va.z; As[lK+3][r] = va.w;
            float4 vb = *(const float4*)&W[(nBase + r)*1024 + k0 + lK];
            Bs[lK+0][r] = vb.x; Bs[lK+1][r] = vb.y;
            Bs[lK+2][r] = vb.z; Bs[lK+3][r] = vb.w;
        }
        __syncthreads();
        #pragma unroll
        for (int kk = 0; kk < 16; kk++) {
            float a[8], b[8];
            *(float4*)&a[0] = *(const float4*)&As[kk][tr*8];
            *(float4*)&a[4] = *(const float4*)&As[kk][tr*8+4];
            *(float4*)&b[0] = *(const float4*)&Bs[kk][tc*8];
            *(float4*)&b[4] = *(const float4*)&Bs[kk][tc*8+4];
            #pragma unroll
            for (int i = 0; i < 8; i++)
                #pragma unroll
                for (int j = 0; j < 8; j++)
                    acc[i][j] += a[i]*b[j];
        }
        __syncthreads();
    }

    const int rBase = mBase + tr*8;
    const int cBase = nBase + tc*8;
    if (mode == 0) {
        #pragma unroll
        for (int i = 0; i < 8; i++) {
            *(float4*)&out[(rBase+i)*1024 + cBase]
                = make_float4(acc[i][0],acc[i][1],acc[i][2],acc[i][3]);
            *(float4*)&out[(rBase+i)*1024 + cBase+4]
                = make_float4(acc[i][4],acc[i][5],acc[i][6],acc[i][7]);
        }
    } else {
        const int h   = cBase >> 6;   // 8-col group never straddles a head
        const int dkB = cBase & 63;
        #pragma unroll
        for (int i = 0; i < 8; i++) {
            int row = rBase + i;
            int b = row >> 11;
            int s = row & 2047;
            float v[8];
            #pragma unroll
            for (int j = 0; j < 8; j++) v[j] = acc[i][j];
            if (mode == 2) {
                int jpB = dkB >> 1;
                #pragma unroll
                for (int jj = 0; jj < 4; jj++) {
                    float cc = g_cos[s*32 + jpB + jj];
                    float sn = g_sin[s*32 + jpB + jj];
                    float ev = acc[i][2*jj], od = acc[i][2*jj+1];
                    v[2*jj]   = ev*cc - od*sn;
                    v[2*jj+1] = od*cc + ev*sn;
                }
            }
            float* dst = &out[(((b*HH + h)*SS) + s)*DK + dkB];
            *(float4*)&dst[0] = make_float4(v[0],v[1],v[2],v[3]);
            *(float4*)&dst[4] = make_float4(v[4],v[5],v[6],v[7]);
        }
    }
}

// ---------------------------------------------------------------------------
// Flash attention, fp32, causal. One CTA = one (b,h) x 64-query block.
// 256 threads as 16x16, 4x4 micro-tile. Online softmax via 16-lane shfl.
// Tiles with kb > qb skipped entirely.
// ---------------------------------------------------------------------------
__global__ __launch_bounds__(256) void flash_kernel(
    const float* __restrict__ Q, const float* __restrict__ K,
    const float* __restrict__ V, float* __restrict__ O)
{
    extern __shared__ __align__(16) float sm[];
    float* QsT = sm;            // [d][r] 64x64
    float* KsT = sm + 4096;     // [d][c]
    float* Vs  = sm + 8192;     // [c][d]
    float* Ps  = sm + 12288;    // [r][c]

    const int qb  = blockIdx.x;   // 0..31
    const int bh  = blockIdx.y;   // 0..31
    const int tid = threadIdx.x;
    const int ty = tid >> 4, tx = tid & 15;

    const float* Qg = Q + bh*SS*DK + qb*64*DK;
    const float* Kg = K + bh*SS*DK;
    const float* Vg = V + bh*SS*DK;

    // Load Q tile transposed (scale 1/sqrt(64)=0.125 folded in)
    {
        int r = tid >> 2, f = tid & 3;
        #pragma unroll
        for (int u = 0; u < 4; u++) {
            int d = 4*(f + 4*u);
            float4 qv = *(const float4*)&Qg[r*64 + d];
            QsT[(d+0)*64 + r] = qv.x * 0.125f;
            QsT[(d+1)*64 + r] = qv.y * 0.125f;
            QsT[(d+2)*64 + r] = qv.z * 0.125f;
            QsT[(d+3)*64 + r] = qv.w * 0.125f;
        }
    }

    float m[4], l[4], o[4][4];
    #pragma unroll
    for (int i = 0; i < 4; i++) {
        m[i] = -1e30f; l[i] = 0.f;
        #pragma unroll
        for (int j = 0; j < 4; j++) o[i][j] = 0.f;
    }

    for (int kb = 0; kb <= qb; kb++) {
        const float* Kt = Kg + kb*64*DK;
        const float* Vt = Vg + kb*64*DK;
        {
            int r = tid >> 2, f = tid & 3;
            #pragma unroll
            for (int u = 0; u < 4; u++) {
                int d = 4*(f + 4*u);
                float4 kv = *(const float4*)&Kt[r*64 + d];
                KsT[(d+0)*64 + r] = kv.x;
                KsT[(d+1)*64 + r] = kv.y;
                KsT[(d+2)*64 + r] = kv.z;
                KsT[(d+3)*64 + r] = kv.w;
            }
            const float4* Vt4 = (const float4*)Vt;
            float4* Vs4 = (float4*)Vs;
            #pragma unroll
            for (int u = 0; u < 4; u++) Vs4[tid + 256*u] = Vt4[tid + 256*u];
        }
        __syncthreads();

        // S = (Q*scale) @ K^T  -> 4x4 per thread
        float s[4][4];
        #pragma unroll
        for (int i = 0; i < 4; i++)
            #pragma unroll
            for (int j = 0; j < 4; j++) s[i][j] = 0.f;
        #pragma unroll 4
        for (int d = 0; d < 64; d++) {
            float4 aa = *(const float4*)&QsT[d*64 + ty*4];
            float4 bb = *(const float4*)&KsT[d*64 + tx*4];
            float a[4] = {aa.x, aa.y, aa.z, aa.w};
            float b[4] = {bb.x, bb.y, bb.z, bb.w};
            #pragma unroll
            for (int i = 0; i < 4; i++)
                #pragma unroll
                for (int j = 0; j < 4; j++)
                    s[i][j] += a[i]*b[j];
        }

        if (kb == qb) {   // diagonal tile: mask c > r
            #pragma unroll
            for (int i = 0; i < 4; i++)
                #pragma unroll
                for (int j = 0; j < 4; j++)
                    if (tx*4 + j > ty*4 + i) s[i][j] = -1e30f;
        }

        // Online softmax (row spread over 16 tx lanes)
        #pragma unroll
        for (int i = 0; i < 4; i++) {
            float mx = fmaxf(fmaxf(s[i][0], s[i][1]), fmaxf(s[i][2], s[i][3]));
            #pragma unroll
            for (int off = 8; off >= 1; off >>= 1)
                mx = fmaxf(mx, __shfl_xor_sync(0xffffffffu, mx, off));
            float mnew = fmaxf(m[i], mx);
            float corr = __expf(m[i] - mnew);
            float sum = 0.f;
            #pragma unroll
            for (int j = 0; j < 4; j++) {
                s[i][j] = __expf(s[i][j] - mnew);
                sum += s[i][j];
            }
            #pragma unroll
            for (int off = 8; off >= 1; off >>= 1)
                sum += __shfl_xor_sync(0xffffffffu, sum, off);
            l[i] = l[i]*corr + sum;
            m[i] = mnew;
            #pragma unroll
            for (int j = 0; j < 4; j++) o[i][j] *= corr;
        }

        // Stage P in smem, then O += P @ V
        #pragma unroll
        for (int i = 0; i < 4; i++)
            *(float4*)&Ps[(ty*4+i)*64 + tx*4]
                = make_float4(s[i][0], s[i][1], s[i][2], s[i][3]);
        __syncthreads();

        #pragma unroll 4
        for (int c4 = 0; c4 < 16; c4++) {
            float vr[4][4], pr[4][4];
            #pragma unroll
            for (int u = 0; u < 4; u++) {
                float4 t = *(const float4*)&Vs[(c4*4+u)*64 + tx*4];
                vr[u][0]=t.x; vr[u][1]=t.y; vr[u][2]=t.z; vr[u][3]=t.w;
            }
            #pragma unroll
            for (int i = 0; i < 4; i++) {
                float4 t = *(const float4*)&Ps[(ty*4+i)*64 + c4*4];
                pr[i][0]=t.x; pr[i][1]=t.y; pr[i][2]=t.z; pr[i][3]=t.w;
            }
            #pragma unroll
            for (int i = 0; i < 4; i++)
                #pragma unroll
                for (int j = 0; j < 4; j++)
                    #pragma unroll
                    for (int u = 0; u < 4; u++)
                        o[i][j] += pr[i][u]*vr[u][j];
        }
        __syncthreads();
    }

    // Write O normalized, directly in [b, s, D] layout
    const int b = bh >> 4, h = bh & 15;
    #pragma unroll
    for (int i = 0; i < 4; i++) {
        float inv = 1.f / l[i];
        int srow = qb*64 + ty*4 + i;
        float4 val = make_float4(o[i][0]*inv, o[i][1]*inv, o[i][2]*inv, o[i][3]*inv);
        *(float4*)&O[(b*SS + srow)*DD + h*DK + tx*4] = val;
    }
}

// ---------------------------------------------------------------------------
extern "C" void kernel_launch(void* const* d_in, const int* in_sizes, int n_in,
                              void* d_out, int out_size) {
    const float* x  = (const float*)d_in[0];
    const float* wq = (const float*)d_in[1];
    const float* wk = (const float*)d_in[2];
    const float* wv = (const float*)d_in[3];
    const float* wo = (const float*)d_in[4];
    float* out = (float*)d_out;

    float *pq, *pk, *pv, *pa;
    cudaGetSymbolAddress((void**)&pq, g_q);
    cudaGetSymbolAddress((void**)&pk, g_k);
    cudaGetSymbolAddress((void**)&pv, g_v);
    cudaGetSymbolAddress((void**)&pa, g_attn);

    cudaFuncSetAttribute(flash_kernel,
                         cudaFuncAttributeMaxDynamicSharedMemorySize, 65536);

    rope_table_kernel<<<64, 1024>>>();

    dim3 gGrid(8, 32);   // N/128 x M/128
    gemm_kernel<<<gGrid, 256>>>(x, wq, pq, 2);   // Q: rope + permute
    gemm_kernel<<<gGrid, 256>>>(x, wk, pk, 2);   // K: rope + permute
    gemm_kernel<<<gGrid, 256>>>(x, wv, pv, 1);   // V: permute

    flash_kernel<<<dim3(32, 32), 256, 65536>>>(pq, pk, pv, pa);

    gemm_kernel<<<gGrid, 256>>>(pa, wo, out, 0); // output projection
}

// round 8
// speedup vs baseline: 1.5974x; 1.5974x over previous
#include <cuda_runtime.h>
#include <cuda_bf16.h>
#include <cstdint>
#include <math.h>

// Problem constants
#define BB 2
#define SS 2048
#define DD 1024
#define HH 16
#define DK 64
#define MM (BB*SS)   // 4096 rows

// Scratch (allocation-free rule: __device__ globals)
__device__ float g_q[BB*HH*SS*DK];     // [b,h,s,dk]
__device__ float g_k[BB*HH*SS*DK];
__device__ float g_v[BB*HH*SS*DK];
__device__ float g_attn[BB*SS*DD];     // [b,s,D]
__device__ float g_cos[SS*(DK/2)];
__device__ float g_sin[SS*(DK/2)];
// bf16 split buffers
__device__ __nv_bfloat16 g_xhi[MM*DD], g_xlo[MM*DD];
__device__ __nv_bfloat16 g_whi[4*DD*DD], g_wlo[4*DD*DD];   // q,k,v,o
__device__ __nv_bfloat16 g_ahi[MM*DD], g_alo[MM*DD];

// ---------------------------------------------------------------------------
// Warp-level tensor-core primitives (portable PTX: sm_80+, compiles for
// compute_103 — tcgen05 is NOT available because the harness emits non-'a'
// PTX target).
// ---------------------------------------------------------------------------
__device__ __forceinline__ uint32_t smem_u32(const void* p) {
    uint32_t a;
    asm("{ .reg .u64 t; cvta.to.shared.u64 t, %1; cvt.u32.u64 %0, t; }"
        : "=r"(a) : "l"(p));
    return a;
}
__device__ __forceinline__ void ldsm_x4(uint32_t& r0, uint32_t& r1,
                                        uint32_t& r2, uint32_t& r3,
                                        uint32_t addr) {
    asm volatile("ldmatrix.sync.aligned.m8n8.x4.shared.b16 {%0,%1,%2,%3}, [%4];"
                 : "=r"(r0), "=r"(r1), "=r"(r2), "=r"(r3) : "r"(addr));
}
__device__ __forceinline__ void mma_bf16(float* d, uint32_t a0, uint32_t a1,
                                         uint32_t a2, uint32_t a3,
                                         uint32_t b0, uint32_t b1) {
    asm volatile(
        "mma.sync.aligned.m16n8k16.row.col.f32.bf16.bf16.f32 "
        "{%0,%1,%2,%3}, {%4,%5,%6,%7}, {%8,%9}, {%0,%1,%2,%3};"
        : "+f"(d[0]), "+f"(d[1]), "+f"(d[2]), "+f"(d[3])
        : "r"(a0), "r"(a1), "r"(a2), "r"(a3), "r"(b0), "r"(b1));
}
__device__ __forceinline__ uint32_t swz128(uint32_t o) { return o ^ ((o >> 3) & 0x70); }

// ---------------------------------------------------------------------------
// RoPE table
// ---------------------------------------------------------------------------
__global__ void rope_table_kernel() {
    int idx = blockIdx.x * blockDim.x + threadIdx.x;
    if (idx >= SS*(DK/2)) return;
    int s = idx >> 5;
    int j = idx & 31;
    double inv = exp(-(double)(2*j) / 64.0 * 9.210340371976184);
    float ang = (float)((double)s * inv);
    g_cos[idx] = cosf(ang);
    g_sin[idx] = sinf(ang);
}

// ---------------------------------------------------------------------------
// fp32 -> bf16 hi/lo split
// ---------------------------------------------------------------------------
__global__ void split_kernel(const float* __restrict__ src,
                             __nv_bfloat16* __restrict__ hi,
                             __nv_bfloat16* __restrict__ lo, int n) {
    int i = (blockIdx.x * blockDim.x + threadIdx.x) * 4;
    if (i >= n) return;
    float4 v = *(const float4*)(src + i);
    __nv_bfloat16 h0 = __float2bfloat16(v.x), h1 = __float2bfloat16(v.y);
    __nv_bfloat16 h2 = __float2bfloat16(v.z), h3 = __float2bfloat16(v.w);
    __nv_bfloat16 l0 = __float2bfloat16(v.x - __bfloat162float(h0));
    __nv_bfloat16 l1 = __float2bfloat16(v.y - __bfloat162float(h1));
    __nv_bfloat16 l2 = __float2bfloat16(v.z - __bfloat162float(h2));
    __nv_bfloat16 l3 = __float2bfloat16(v.w - __bfloat162float(h3));
    *(__nv_bfloat162*)(hi + i)     = __nv_bfloat162(h0, h1);
    *(__nv_bfloat162*)(hi + i + 2) = __nv_bfloat162(h2, h3);
    *(__nv_bfloat162*)(lo + i)     = __nv_bfloat162(l0, l1);
    *(__nv_bfloat162*)(lo + i + 2) = __nv_bfloat162(l2, l3);
}

// ---------------------------------------------------------------------------
// Tensor-core GEMM via mma.sync bf16 (fp32 accum):
//   C[m][n] = sum_k A[m][k]*W[n][k]
// fp32 emulated with 2-way bf16 split: A_hi*W_hi + A_lo*W_hi + A_hi*W_lo
// (3 passes accumulated in registers).
// CTA tile 128x128, 8 warps each 64x32, K-chunk 64 (one SW128 row).
// mode 0: row-major write; mode 1: [b,h,s,dk] permute; mode 2: + RoPE
// ---------------------------------------------------------------------------
__global__ __launch_bounds__(256) void tcgemm_kernel(
    const __nv_bfloat16* __restrict__ Ahi, const __nv_bfloat16* __restrict__ Alo,
    const __nv_bfloat16* __restrict__ Bhi, const __nv_bfloat16* __restrict__ Blo,
    float* __restrict__ out, int mode)
{
    __shared__ __align__(1024) char smem[2 * 16384];   // A tile + B tile
    const uint32_t sbA = smem_u32(smem);
    const uint32_t sbB = sbA + 16384;

    const int tid  = threadIdx.x;
    const int wid  = tid >> 5, lane = tid & 31;
    const int mBase = blockIdx.y * 128;
    const int nBase = blockIdx.x * 128;
    const int warp_m = wid >> 2;        // 0..1 -> 64 rows
    const int warp_n = wid & 3;         // 0..3 -> 32 cols

    // accumulators: [mt(4 x m16)][nt(4 x n8)][4]
    float acc[4][4][4];
    #pragma unroll
    for (int i = 0; i < 4; i++)
        #pragma unroll
        for (int j = 0; j < 4; j++)
            #pragma unroll
            for (int q = 0; q < 4; q++) acc[i][j][q] = 0.f;

    // smem-load indexing (same as R6): 4 rows x 16B per thread per tile
    const int lrow = tid >> 3;          // 0..31
    const int lseg = tid & 7;           // 16B segment in 128B row

    // ldmatrix lane address components
    const int aRow = lane & 15;            // A: rows 0..15 within m16 tile
    const int aSeg = lane >> 4;            // A: k-halves
    const int bRow = (lane & 7) + ((lane & 16) ? 8 : 0);  // B: n-row in 16-grp
    const int bSeg = (lane >> 3) & 1;

    for (int c = 0; c < 48; c++) {
        const int pass = c >> 4;        // 0,1,2
        const int k0 = (c & 15) * 64;
        const __nv_bfloat16* __restrict__ As = (pass == 1) ? Alo : Ahi;
        const __nv_bfloat16* __restrict__ Bs = (pass == 2) ? Blo : Bhi;

        #pragma unroll
        for (int i = 0; i < 4; i++) {
            int row = lrow + i * 32;
            uint32_t so = swz128((uint32_t)(row * 128 + lseg * 16));
            *(uint4*)(smem + so) =
                *(const uint4*)(As + (size_t)(mBase + row) * DD + k0 + lseg * 8);
            *(uint4*)(smem + 16384 + so) =
                *(const uint4*)(Bs + (size_t)(nBase + row) * DD + k0 + lseg * 8);
        }
        __syncthreads();

        #pragma unroll
        for (int ks = 0; ks < 4; ks++) {
            uint32_t af[4][4];
            #pragma unroll
            for (int mt = 0; mt < 4; mt++) {
                uint32_t off = swz128((uint32_t)((warp_m*64 + mt*16 + aRow)*128
                                                  + ks*32 + aSeg*16));
                ldsm_x4(af[mt][0], af[mt][1], af[mt][2], af[mt][3], sbA + off);
            }
            uint32_t bf[2][4];
            #pragma unroll
            for (int nt2 = 0; nt2 < 2; nt2++) {
                uint32_t off = swz128((uint32_t)((warp_n*32 + nt2*16 + bRow)*128
                                                  + ks*32 + bSeg*16));
                ldsm_x4(bf[nt2][0], bf[nt2][1], bf[nt2][2], bf[nt2][3], sbB + off);
            }
            #pragma unroll
            for (int mt = 0; mt < 4; mt++) {
                mma_bf16(acc[mt][0], af[mt][0],af[mt][1],af[mt][2],af[mt][3],
                         bf[0][0], bf[0][1]);
                mma_bf16(acc[mt][1], af[mt][0],af[mt][1],af[mt][2],af[mt][3],
                         bf[0][2], bf[0][3]);
                mma_bf16(acc[mt][2], af[mt][0],af[mt][1],af[mt][2],af[mt][3],
                         bf[1][0], bf[1][1]);
                mma_bf16(acc[mt][3], af[mt][0],af[mt][1],af[mt][2],af[mt][3],
                         bf[1][2], bf[1][3]);
            }
        }
        __syncthreads();
    }

    // Epilogue. C fragment: (d0,d1) -> row r0, cols (c0,c0+1); (d2,d3) -> r0+8.
    const int rQuad = lane >> 2;           // 0..7
    const int cPair = (lane & 3) * 2;      // 0,2,4,6

    #pragma unroll
    for (int mt = 0; mt < 4; mt++) {
        #pragma unroll
        for (int nt = 0; nt < 4; nt++) {
            const int col = nBase + warp_n*32 + nt*8 + cPair;   // even
            #pragma unroll
            for (int hrow = 0; hrow < 2; hrow++) {
                const int row = mBase + warp_m*64 + mt*16 + rQuad + hrow*8;
                float e = acc[mt][nt][hrow*2 + 0];
                float o = acc[mt][nt][hrow*2 + 1];
                if (mode == 0) {
                    *(float2*)(out + (size_t)row * DD + col) = make_float2(e, o);
                } else {
                    const int b = row >> 11, s = row & 2047;
                    const int h = col >> 6, dk = col & 63;
                    if (mode == 2) {
                        float cc = g_cos[s*32 + (dk >> 1)];
                        float sn = g_sin[s*32 + (dk >> 1)];
                        float ev = e * cc - o * sn;
                        float od = o * cc + e * sn;
                        e = ev; o = od;
                    }
                    *(float2*)(out + ((size_t)((b*HH + h)*SS + s)) * DK + dk)
                        = make_float2(e, o);
                }
            }
        }
    }
}

// ---------------------------------------------------------------------------
// Flash attention, fp32, causal (unchanged — R6 passing version)
// ---------------------------------------------------------------------------
__global__ __launch_bounds__(256) void flash_kernel(
    const float* __restrict__ Q, const float* __restrict__ K,
    const float* __restrict__ V, float* __restrict__ O)
{
    extern __shared__ __align__(16) float sm[];
    float* QsT = sm;
    float* KsT = sm + 4096;
    float* Vs  = sm + 8192;
    float* Ps  = sm + 12288;

    const int qb  = blockIdx.x;
    const int bh  = blockIdx.y;
    const int tid = threadIdx.x;
    const int ty = tid >> 4, tx = tid & 15;

    const float* Qg = Q + bh*SS*DK + qb*64*DK;
    const float* Kg = K + bh*SS*DK;
    const float* Vg = V + bh*SS*DK;

    {
        int r = tid >> 2, f = tid & 3;
        #pragma unroll
        for (int u = 0; u < 4; u++) {
            int d = 4*(f + 4*u);
            float4 qv = *(const float4*)&Qg[r*64 + d];
            QsT[(d+0)*64 + r] = qv.x * 0.125f;
            QsT[(d+1)*64 + r] = qv.y * 0.125f;
            QsT[(d+2)*64 + r] = qv.z * 0.125f;
            QsT[(d+3)*64 + r] = qv.w * 0.125f;
        }
    }

    float m[4], l[4], o[4][4];
    #pragma unroll
    for (int i = 0; i < 4; i++) {
        m[i] = -1e30f; l[i] = 0.f;
        #pragma unroll
        for (int j = 0; j < 4; j++) o[i][j] = 0.f;
    }

    for (int kb = 0; kb <= qb; kb++) {
        const float* Kt = Kg + kb*64*DK;
        const float* Vt = Vg + kb*64*DK;
        {
            int r = tid >> 2, f = tid & 3;
            #pragma unroll
            for (int u = 0; u < 4; u++) {
                int d = 4*(f + 4*u);
                float4 kv = *(const float4*)&Kt[r*64 + d];
                KsT[(d+0)*64 + r] = kv.x;
                KsT[(d+1)*64 + r] = kv.y;
                KsT[(d+2)*64 + r] = kv.z;
                KsT[(d+3)*64 + r] = kv.w;
            }
            const float4* Vt4 = (const float4*)Vt;
            float4* Vs4 = (float4*)Vs;
            #pragma unroll
            for (int u = 0; u < 4; u++) Vs4[tid + 256*u] = Vt4[tid + 256*u];
        }
        __syncthreads();

        float s[4][4];
        #pragma unroll
        for (int i = 0; i < 4; i++)
            #pragma unroll
            for (int j = 0; j < 4; j++) s[i][j] = 0.f;
        #pragma unroll 4
        for (int d = 0; d < 64; d++) {
            float4 aa = *(const float4*)&QsT[d*64 + ty*4];
            float4 bb = *(const float4*)&KsT[d*64 + tx*4];
            float a[4] = {aa.x, aa.y, aa.z, aa.w};
            float b[4] = {bb.x, bb.y, bb.z, bb.w};
            #pragma unroll
            for (int i = 0; i < 4; i++)
                #pragma unroll
                for (int j = 0; j < 4; j++)
                    s[i][j] += a[i]*b[j];
        }

        if (kb == qb) {
            #pragma unroll
            for (int i = 0; i < 4; i++)
                #pragma unroll
                for (int j = 0; j < 4; j++)
                    if (tx*4 + j > ty*4 + i) s[i][j] = -1e30f;
        }

        #pragma unroll
        for (int i = 0; i < 4; i++) {
            float mx = fmaxf(fmaxf(s[i][0], s[i][1]), fmaxf(s[i][2], s[i][3]));
            #pragma unroll
            for (int off = 8; off >= 1; off >>= 1)
                mx = fmaxf(mx, __shfl_xor_sync(0xffffffffu, mx, off));
            float mnew = fmaxf(m[i], mx);
            float corr = __expf(m[i] - mnew);
            float sum = 0.f;
            #pragma unroll
            for (int j = 0; j < 4; j++) {
                s[i][j] = __expf(s[i][j] - mnew);
                sum += s[i][j];
            }
            #pragma unroll
            for (int off = 8; off >= 1; off >>= 1)
                sum += __shfl_xor_sync(0xffffffffu, sum, off);
            l[i] = l[i]*corr + sum;
            m[i] = mnew;
            #pragma unroll
            for (int j = 0; j < 4; j++) o[i][j] *= corr;
        }

        #pragma unroll
        for (int i = 0; i < 4; i++)
            *(float4*)&Ps[(ty*4+i)*64 + tx*4]
                = make_float4(s[i][0], s[i][1], s[i][2], s[i][3]);
        __syncthreads();

        #pragma unroll 4
        for (int c4 = 0; c4 < 16; c4++) {
            float vr[4][4], pr[4][4];
            #pragma unroll
            for (int u = 0; u < 4; u++) {
                float4 t = *(const float4*)&Vs[(c4*4+u)*64 + tx*4];
                vr[u][0]=t.x; vr[u][1]=t.y; vr[u][2]=t.z; vr[u][3]=t.w;
            }
            #pragma unroll
            for (int i = 0; i < 4; i++) {
                float4 t = *(const float4*)&Ps[(ty*4+i)*64 + c4*4];
                pr[i][0]=t.x; pr[i][1]=t.y; pr[i][2]=t.z; pr[i][3]=t.w;
            }
            #pragma unroll
            for (int i = 0; i < 4; i++)
                #pragma unroll
                for (int j = 0; j < 4; j++)
                    #pragma unroll
                    for (int u = 0; u < 4; u++)
                        o[i][j] += pr[i][u]*vr[u][j];
        }
        __syncthreads();
    }

    const int b = bh >> 4, h = bh & 15;
    #pragma unroll
    for (int i = 0; i < 4; i++) {
        float inv = 1.f / l[i];
        int srow = qb*64 + ty*4 + i;
        float4 val = make_float4(o[i][0]*inv, o[i][1]*inv, o[i][2]*inv, o[i][3]*inv);
        *(float4*)&O[(b*SS + srow)*DD + h*DK + tx*4] = val;
    }
}

// ---------------------------------------------------------------------------
extern "C" void kernel_launch(void* const* d_in, const int* in_sizes, int n_in,
                              void* d_out, int out_size) {
    const float* x  = (const float*)d_in[0];
    const float* wq = (const float*)d_in[1];
    const float* wk = (const float*)d_in[2];
    const float* wv = (const float*)d_in[3];
    const float* wo = (const float*)d_in[4];
    float* out = (float*)d_out;

    float *pq, *pk, *pv, *pa;
    __nv_bfloat16 *pxh, *pxl, *pwh, *pwl, *pah, *pal;
    cudaGetSymbolAddress((void**)&pq,  g_q);
    cudaGetSymbolAddress((void**)&pk,  g_k);
    cudaGetSymbolAddress((void**)&pv,  g_v);
    cudaGetSymbolAddress((void**)&pa,  g_attn);
    cudaGetSymbolAddress((void**)&pxh, g_xhi);
    cudaGetSymbolAddress((void**)&pxl, g_xlo);
    cudaGetSymbolAddress((void**)&pwh, g_whi);
    cudaGetSymbolAddress((void**)&pwl, g_wlo);
    cudaGetSymbolAddress((void**)&pah, g_ahi);
    cudaGetSymbolAddress((void**)&pal, g_alo);

    cudaFuncSetAttribute(flash_kernel,
                         cudaFuncAttributeMaxDynamicSharedMemorySize, 65536);

    rope_table_kernel<<<64, 1024>>>();

    const int nx = MM * DD;      // 4M
    const int nw = DD * DD;      // 1M
    split_kernel<<<nx/1024, 256>>>(x,  pxh, pxl, nx);
    split_kernel<<<nw/1024, 256>>>(wq, pwh + 0*nw, pwl + 0*nw, nw);
    split_kernel<<<nw/1024, 256>>>(wk, pwh + 1*nw, pwl + 1*nw, nw);
    split_kernel<<<nw/1024, 256>>>(wv, pwh + 2*nw, pwl + 2*nw, nw);
    split_kernel<<<nw/1024, 256>>>(wo, pwh + 3*nw, pwl + 3*nw, nw);

    dim3 gGrid(8, 32);   // N/128 x M/128
    tcgemm_kernel<<<gGrid, 256>>>(pxh, pxl, pwh + 0*nw, pwl + 0*nw, pq, 2);
    tcgemm_kernel<<<gGrid, 256>>>(pxh, pxl, pwh + 1*nw, pwl + 1*nw, pk, 2);
    tcgemm_kernel<<<gGrid, 256>>>(pxh, pxl, pwh + 2*nw, pwl + 2*nw, pv, 1);

    flash_kernel<<<dim3(32, 32), 256, 65536>>>(pq, pk, pv, pa);

    split_kernel<<<nx/1024, 256>>>(pa, pah, pal, nx);
    tcgemm_kernel<<<gGrid, 256>>>(pah, pal, pwh + 3*nw, pwl + 3*nw, out, 0);
}

// round 9
// speedup vs baseline: 2.8719x; 1.7978x over previous
#include <cuda_runtime.h>
#include <cuda_bf16.h>
#include <cstdint>
#include <math.h>

// Problem constants
#define BB 2
#define SS 2048
#define DD 1024
#define HH 16
#define DK 64
#define MM (BB*SS)   // 4096 rows

// Scratch (allocation-free rule: __device__ globals)
__device__ __nv_bfloat16 g_qh[BB*HH*SS*DK];   // [b,h,s,dk] bf16 (rope, x0.125)
__device__ __nv_bfloat16 g_kh[BB*HH*SS*DK];   // [b,h,s,dk] bf16 (rope)
__device__ __nv_bfloat16 g_vh[BB*HH*SS*DK];   // [b,h,s,dk] bf16 hi
__device__ __nv_bfloat16 g_vl[BB*HH*SS*DK];   // [b,h,s,dk] bf16 lo
__device__ float g_cos[SS*(DK/2)];
__device__ float g_sin[SS*(DK/2)];
// bf16 split buffers for GEMM inputs
__device__ __nv_bfloat16 g_xhi[MM*DD], g_xlo[MM*DD];
__device__ __nv_bfloat16 g_whi[4*DD*DD], g_wlo[4*DD*DD];   // q,k,v,o
__device__ __nv_bfloat16 g_ahi[MM*DD], g_alo[MM*DD];       // attn out hi/lo

// ---------------------------------------------------------------------------
// Warp-level tensor-core primitives (portable PTX, compiles for compute_103)
// ---------------------------------------------------------------------------
__device__ __forceinline__ uint32_t smem_u32(const void* p) {
    uint32_t a;
    asm("{ .reg .u64 t; cvta.to.shared.u64 t, %1; cvt.u32.u64 %0, t; }"
        : "=r"(a) : "l"(p));
    return a;
}
__device__ __forceinline__ void ldsm_x4(uint32_t& r0, uint32_t& r1,
                                        uint32_t& r2, uint32_t& r3,
                                        uint32_t addr) {
    asm volatile("ldmatrix.sync.aligned.m8n8.x4.shared.b16 {%0,%1,%2,%3}, [%4];"
                 : "=r"(r0), "=r"(r1), "=r"(r2), "=r"(r3) : "r"(addr));
}
__device__ __forceinline__ void ldsm_x4t(uint32_t& r0, uint32_t& r1,
                                         uint32_t& r2, uint32_t& r3,
                                         uint32_t addr) {
    asm volatile("ldmatrix.sync.aligned.m8n8.x4.trans.shared.b16 {%0,%1,%2,%3}, [%4];"
                 : "=r"(r0), "=r"(r1), "=r"(r2), "=r"(r3) : "r"(addr));
}
__device__ __forceinline__ void mma_bf16(float* d, uint32_t a0, uint32_t a1,
                                         uint32_t a2, uint32_t a3,
                                         uint32_t b0, uint32_t b1) {
    asm volatile(
        "mma.sync.aligned.m16n8k16.row.col.f32.bf16.bf16.f32 "
        "{%0,%1,%2,%3}, {%4,%5,%6,%7}, {%8,%9}, {%0,%1,%2,%3};"
        : "+f"(d[0]), "+f"(d[1]), "+f"(d[2]), "+f"(d[3])
        : "r"(a0), "r"(a1), "r"(a2), "r"(a3), "r"(b0), "r"(b1));
}
__device__ __forceinline__ uint32_t swz128(uint32_t o) { return o ^ ((o >> 3) & 0x70); }
__device__ __forceinline__ uint32_t pack_bf2(float a, float b) {
    __nv_bfloat162 t(__float2bfloat16(a), __float2bfloat16(b));
    return *(uint32_t*)&t;
}

// ---------------------------------------------------------------------------
// RoPE table
// ---------------------------------------------------------------------------
__global__ void rope_table_kernel() {
    int idx = blockIdx.x * blockDim.x + threadIdx.x;
    if (idx >= SS*(DK/2)) return;
    int s = idx >> 5;
    int j = idx & 31;
    double inv = exp(-(double)(2*j) / 64.0 * 9.210340371976184);
    float ang = (float)((double)s * inv);
    g_cos[idx] = cosf(ang);
    g_sin[idx] = sinf(ang);
}

// ---------------------------------------------------------------------------
// fp32 -> bf16 hi/lo split
// ---------------------------------------------------------------------------
__global__ void split_kernel(const float* __restrict__ src,
                             __nv_bfloat16* __restrict__ hi,
                             __nv_bfloat16* __restrict__ lo, int n) {
    int i = (blockIdx.x * blockDim.x + threadIdx.x) * 4;
    if (i >= n) return;
    float4 v = *(const float4*)(src + i);
    __nv_bfloat16 h0 = __float2bfloat16(v.x), h1 = __float2bfloat16(v.y);
    __nv_bfloat16 h2 = __float2bfloat16(v.z), h3 = __float2bfloat16(v.w);
    __nv_bfloat16 l0 = __float2bfloat16(v.x - __bfloat162float(h0));
    __nv_bfloat16 l1 = __float2bfloat16(v.y - __bfloat162float(h1));
    __nv_bfloat16 l2 = __float2bfloat16(v.z - __bfloat162float(h2));
    __nv_bfloat16 l3 = __float2bfloat16(v.w - __bfloat162float(h3));
    *(__nv_bfloat162*)(hi + i)     = __nv_bfloat162(h0, h1);
    *(__nv_bfloat162*)(hi + i + 2) = __nv_bfloat162(h2, h3);
    *(__nv_bfloat162*)(lo + i)     = __nv_bfloat162(l0, l1);
    *(__nv_bfloat162*)(lo + i + 2) = __nv_bfloat162(l2, l3);
}

// ---------------------------------------------------------------------------
// Tensor-core GEMM, C[m][n] = sum_k A[m][k]*W[n][k], fp32 via 2-way bf16
// split (3 accumulated passes). CTA 128x128, 8 warps 64x32, K-chunk 64.
// mode 0: fp32 row-major to fout
// mode 1: V -> bf16 hi/lo [b,h,s,dk] (oh, ol)
// mode 2: Q -> rope, x0.125, bf16 [b,h,s,dk] (oh)
// mode 3: K -> rope, bf16 [b,h,s,dk] (oh)
// ---------------------------------------------------------------------------
__global__ __launch_bounds__(256) void tcgemm_kernel(
    const __nv_bfloat16* __restrict__ Ahi, const __nv_bfloat16* __restrict__ Alo,
    const __nv_bfloat16* __restrict__ Bhi, const __nv_bfloat16* __restrict__ Blo,
    float* __restrict__ fout, __nv_bfloat16* __restrict__ oh,
    __nv_bfloat16* __restrict__ ol, int mode)
{
    __shared__ __align__(1024) char smem[2 * 16384];
    const uint32_t sbA = smem_u32(smem);
    const uint32_t sbB = sbA + 16384;

    const int tid  = threadIdx.x;
    const int wid  = tid >> 5, lane = tid & 31;
    const int mBase = blockIdx.y * 128;
    const int nBase = blockIdx.x * 128;
    const int warp_m = wid >> 2;
    const int warp_n = wid & 3;

    float acc[4][4][4];
    #pragma unroll
    for (int i = 0; i < 4; i++)
        #pragma unroll
        for (int j = 0; j < 4; j++)
            #pragma unroll
            for (int q = 0; q < 4; q++) acc[i][j][q] = 0.f;

    const int lrow = tid >> 3;
    const int lseg = tid & 7;
    const int aRow = lane & 15;
    const int aSeg = lane >> 4;
    const int bRow = (lane & 7) + ((lane & 16) ? 8 : 0);
    const int bSeg = (lane >> 3) & 1;

    for (int c = 0; c < 48; c++) {
        const int pass = c >> 4;
        const int k0 = (c & 15) * 64;
        const __nv_bfloat16* __restrict__ As = (pass == 1) ? Alo : Ahi;
        const __nv_bfloat16* __restrict__ Bs = (pass == 2) ? Blo : Bhi;

        #pragma unroll
        for (int i = 0; i < 4; i++) {
            int row = lrow + i * 32;
            uint32_t so = swz128((uint32_t)(row * 128 + lseg * 16));
            *(uint4*)(smem + so) =
                *(const uint4*)(As + (size_t)(mBase + row) * DD + k0 + lseg * 8);
            *(uint4*)(smem + 16384 + so) =
                *(const uint4*)(Bs + (size_t)(nBase + row) * DD + k0 + lseg * 8);
        }
        __syncthreads();

        #pragma unroll
        for (int ks = 0; ks < 4; ks++) {
            uint32_t af[4][4];
            #pragma unroll
            for (int mt = 0; mt < 4; mt++) {
                uint32_t off = swz128((uint32_t)((warp_m*64 + mt*16 + aRow)*128
                                                  + ks*32 + aSeg*16));
                ldsm_x4(af[mt][0], af[mt][1], af[mt][2], af[mt][3], sbA + off);
            }
            uint32_t bf[2][4];
            #pragma unroll
            for (int nt2 = 0; nt2 < 2; nt2++) {
                uint32_t off = swz128((uint32_t)((warp_n*32 + nt2*16 + bRow)*128
                                                  + ks*32 + bSeg*16));
                ldsm_x4(bf[nt2][0], bf[nt2][1], bf[nt2][2], bf[nt2][3], sbB + off);
            }
            #pragma unroll
            for (int mt = 0; mt < 4; mt++) {
                mma_bf16(acc[mt][0], af[mt][0],af[mt][1],af[mt][2],af[mt][3],
                         bf[0][0], bf[0][1]);
                mma_bf16(acc[mt][1], af[mt][0],af[mt][1],af[mt][2],af[mt][3],
                         bf[0][2], bf[0][3]);
                mma_bf16(acc[mt][2], af[mt][0],af[mt][1],af[mt][2],af[mt][3],
                         bf[1][0], bf[1][1]);
                mma_bf16(acc[mt][3], af[mt][0],af[mt][1],af[mt][2],af[mt][3],
                         bf[1][2], bf[1][3]);
            }
        }
        __syncthreads();
    }

    const int rQuad = lane >> 2;
    const int cPair = (lane & 3) * 2;

    #pragma unroll
    for (int mt = 0; mt < 4; mt++) {
        #pragma unroll
        for (int nt = 0; nt < 4; nt++) {
            const int col = nBase + warp_n*32 + nt*8 + cPair;
            #pragma unroll
            for (int hrow = 0; hrow < 2; hrow++) {
                const int row = mBase + warp_m*64 + mt*16 + rQuad + hrow*8;
                float e = acc[mt][nt][hrow*2 + 0];
                float o = acc[mt][nt][hrow*2 + 1];
                if (mode == 0) {
                    *(float2*)(fout + (size_t)row * DD + col) = make_float2(e, o);
                } else {
                    const int b = row >> 11, s = row & 2047;
                    const int h = col >> 6, dk = col & 63;
                    if (mode >= 2) {   // RoPE
                        float cc = g_cos[s*32 + (dk >> 1)];
                        float sn = g_sin[s*32 + (dk >> 1)];
                        float ev = e * cc - o * sn;
                        float od = o * cc + e * sn;
                        e = ev; o = od;
                        if (mode == 2) { e *= 0.125f; o *= 0.125f; }
                    }
                    size_t idx = ((size_t)((b*HH + h)*SS + s)) * DK + dk;
                    __nv_bfloat16 eh = __float2bfloat16(e);
                    __nv_bfloat16 oh2 = __float2bfloat16(o);
                    *(__nv_bfloat162*)(oh + idx) = __nv_bfloat162(eh, oh2);
                    if (mode == 1) {
                        __nv_bfloat16 el = __float2bfloat16(e - __bfloat162float(eh));
                        __nv_bfloat16 ol2 = __float2bfloat16(o - __bfloat162float(oh2));
                        *(__nv_bfloat162*)(ol + idx) = __nv_bfloat162(el, ol2);
                    }
                }
            }
        }
    }
}

// ---------------------------------------------------------------------------
// Tensor-core flash attention, causal.
// 1 CTA = (b,h) x 64 queries; 4 warps x 16 query rows; 64-key tiles.
// QK^T: plain bf16 (scores ~1e-3 => quantization error ~3e-6 abs, negligible).
// PV: 2-way split (Phi*Vhi + Plo*Vhi + Phi*Vlo), fp32 accum.
// Output written pre-split (bf16 hi/lo) in [b,s,D] for the final GEMM.
// ---------------------------------------------------------------------------
__global__ __launch_bounds__(128) void flash_tc_kernel(
    const __nv_bfloat16* __restrict__ Qh, const __nv_bfloat16* __restrict__ Kh,
    const __nv_bfloat16* __restrict__ Vh, const __nv_bfloat16* __restrict__ Vl,
    __nv_bfloat16* __restrict__ Oh, __nv_bfloat16* __restrict__ Ol)
{
    __shared__ __align__(1024) char smem[4 * 8192];   // Qs, Ks, Vhs, Vls
    const uint32_t sQ  = smem_u32(smem);
    const uint32_t sK  = sQ + 8192;
    const uint32_t sVh = sQ + 16384;
    const uint32_t sVl = sQ + 24576;

    const int qb  = gridDim.x - 1 - blockIdx.x;   // schedule big tiles first
    const int bh  = blockIdx.y;
    const int tid = threadIdx.x;
    const int warp = tid >> 5, lane = tid & 31;
    const int quad = lane >> 2, t4 = lane & 3;

    const __nv_bfloat16* Qg  = Qh + ((size_t)bh*SS + qb*64)*DK;
    const __nv_bfloat16* Kg  = Kh + (size_t)bh*SS*DK;
    const __nv_bfloat16* Vhg = Vh + (size_t)bh*SS*DK;
    const __nv_bfloat16* Vlg = Vl + (size_t)bh*SS*DK;

    // Load Q tile (64 rows x 128B), swizzled
    {
        int r = tid >> 1, s0 = (tid & 1) * 4;
        #pragma unroll
        for (int u = 0; u < 4; u++) {
            uint32_t so = swz128((uint32_t)(r*128 + (s0+u)*16));
            *(uint4*)(smem + so) = *(const uint4*)(Qg + (size_t)r*DK + (s0+u)*8);
        }
    }
    __syncthreads();

    // Hoist Q a-frags (4 k-steps), loaded once
    uint32_t qf[4][4];
    {
        const int aRow = lane & 15, aSeg = lane >> 4;
        #pragma unroll
        for (int ks = 0; ks < 4; ks++) {
            uint32_t off = swz128((uint32_t)((warp*16 + aRow)*128 + ks*32 + aSeg*16));
            ldsm_x4(qf[ks][0], qf[ks][1], qf[ks][2], qf[ks][3], sQ + off);
        }
    }

    float m[2] = {-1e30f, -1e30f}, l[2] = {0.f, 0.f};
    float acc[8][4];
    #pragma unroll
    for (int nt = 0; nt < 8; nt++)
        #pragma unroll
        for (int q = 0; q < 4; q++) acc[nt][q] = 0.f;

    const int bRow = (lane & 7) + ((lane & 16) ? 8 : 0);
    const int bSeg = (lane >> 3) & 1;
    const int vmi = lane >> 3, vrow = lane & 7;   // V trans-ldmatrix lanes

    for (int kb = 0; kb <= qb; kb++) {
        // Load K, Vhi, Vlo tiles
        {
            int r = tid >> 1, s0 = (tid & 1) * 4;
            size_t gro = (size_t)(kb*64 + r) * DK;
            #pragma unroll
            for (int u = 0; u < 4; u++) {
                uint32_t so = swz128((uint32_t)(r*128 + (s0+u)*16));
                *(uint4*)(smem + 8192  + so) = *(const uint4*)(Kg  + gro + (s0+u)*8);
                *(uint4*)(smem + 16384 + so) = *(const uint4*)(Vhg + gro + (s0+u)*8);
                *(uint4*)(smem + 24576 + so) = *(const uint4*)(Vlg + gro + (s0+u)*8);
            }
        }
        __syncthreads();

        // S = Q K^T (one bf16 pass)
        float s[8][4];
        #pragma unroll
        for (int nt = 0; nt < 8; nt++)
            #pragma unroll
            for (int q = 0; q < 4; q++) s[nt][q] = 0.f;
        #pragma unroll
        for (int ks = 0; ks < 4; ks++) {
            #pragma unroll
            for (int g = 0; g < 4; g++) {
                uint32_t k0, k1, k2, k3;
                uint32_t off = swz128((uint32_t)((g*16 + bRow)*128 + ks*32 + bSeg*16));
                ldsm_x4(k0, k1, k2, k3, sK + off);
                mma_bf16(s[g*2],   qf[ks][0],qf[ks][1],qf[ks][2],qf[ks][3], k0, k1);
                mma_bf16(s[g*2+1], qf[ks][0],qf[ks][1],qf[ks][2],qf[ks][3], k2, k3);
            }
        }

        // Causal mask on the diagonal tile
        if (kb == qb) {
            #pragma unroll
            for (int nt = 0; nt < 8; nt++)
                #pragma unroll
                for (int e = 0; e < 4; e++) {
                    int qrow = warp*16 + quad + (e >> 1)*8;
                    int kcol = nt*8 + t4*2 + (e & 1);
                    if (kcol > qrow) s[nt][e] = -1e30f;
                }
        }

        // Online softmax (rows quad, quad+8; 4 lanes per row share via shfl)
        float corr[2];
        #pragma unroll
        for (int hr = 0; hr < 2; hr++) {
            float mx = -1e30f;
            #pragma unroll
            for (int nt = 0; nt < 8; nt++)
                mx = fmaxf(mx, fmaxf(s[nt][hr*2], s[nt][hr*2+1]));
            mx = fmaxf(mx, __shfl_xor_sync(0xffffffffu, mx, 1));
            mx = fmaxf(mx, __shfl_xor_sync(0xffffffffu, mx, 2));
            float mn = fmaxf(m[hr], mx);
            corr[hr] = __expf(m[hr] - mn);
            m[hr] = mn;
            float sum = 0.f;
            #pragma unroll
            for (int nt = 0; nt < 8; nt++) {
                float p0 = __expf(s[nt][hr*2]   - mn);
                float p1 = __expf(s[nt][hr*2+1] - mn);
                s[nt][hr*2] = p0; s[nt][hr*2+1] = p1;
                sum += p0 + p1;
            }
            sum += __shfl_xor_sync(0xffffffffu, sum, 1);
            sum += __shfl_xor_sync(0xffffffffu, sum, 2);
            l[hr] = l[hr]*corr[hr] + sum;
        }
        #pragma unroll
        for (int nt = 0; nt < 8; nt++) {
            acc[nt][0] *= corr[0]; acc[nt][1] *= corr[0];
            acc[nt][2] *= corr[1]; acc[nt][3] *= corr[1];
        }

        // P -> bf16 hi/lo fragments (a-frag layout reuse)
        uint32_t phi[8][2], plo[8][2];
        #pragma unroll
        for (int nt = 0; nt < 8; nt++) {
            float f0 = s[nt][0], f1 = s[nt][1], f2 = s[nt][2], f3 = s[nt][3];
            phi[nt][0] = pack_bf2(f0, f1);
            phi[nt][1] = pack_bf2(f2, f3);
            __nv_bfloat162 h0 = *(__nv_bfloat162*)&phi[nt][0];
            __nv_bfloat162 h1 = *(__nv_bfloat162*)&phi[nt][1];
            plo[nt][0] = pack_bf2(f0 - __bfloat162float(h0.x),
                                  f1 - __bfloat162float(h0.y));
            plo[nt][1] = pack_bf2(f2 - __bfloat162float(h1.x),
                                  f3 - __bfloat162float(h1.y));
        }

        // O += Phi*Vhi + Plo*Vhi + Phi*Vlo
        #pragma unroll
        for (int kt = 0; kt < 4; kt++) {
            uint32_t ah0 = phi[2*kt][0], ah1 = phi[2*kt][1];
            uint32_t ah2 = phi[2*kt+1][0], ah3 = phi[2*kt+1][1];
            uint32_t al0 = plo[2*kt][0], al1 = plo[2*kt][1];
            uint32_t al2 = plo[2*kt+1][0], al3 = plo[2*kt+1][1];
            #pragma unroll
            for (int g = 0; g < 4; g++) {
                uint32_t off = swz128((uint32_t)(
                    (kt*16 + (vmi & 1)*8 + vrow)*128 + (g*16 + (vmi >> 1)*8)*2));
                uint32_t vh0, vh1, vh2, vh3, vl0, vl1, vl2, vl3;
                ldsm_x4t(vh0, vh1, vh2, vh3, sVh + off);
                ldsm_x4t(vl0, vl1, vl2, vl3, sVl + off);
                mma_bf16(acc[g*2],   ah0,ah1,ah2,ah3, vh0, vh1);
                mma_bf16(acc[g*2+1], ah0,ah1,ah2,ah3, vh2, vh3);
                mma_bf16(acc[g*2],   al0,al1,al2,al3, vh0, vh1);
                mma_bf16(acc[g*2+1], al0,al1,al2,al3, vh2, vh3);
                mma_bf16(acc[g*2],   ah0,ah1,ah2,ah3, vl0, vl1);
                mma_bf16(acc[g*2+1], ah0,ah1,ah2,ah3, vl2, vl3);
            }
        }
        __syncthreads();
    }

    // Epilogue: O/l, write bf16 hi/lo in [b,s,D]
    const int b = bh >> 4, h = bh & 15;
    #pragma unroll
    for (int hr = 0; hr < 2; hr++) {
        float inv = 1.f / l[hr];
        int srow = qb*64 + warp*16 + quad + hr*8;
        #pragma unroll
        for (int nt = 0; nt < 8; nt++) {
            float e = acc[nt][hr*2]   * inv;
            float o = acc[nt][hr*2+1] * inv;
            __nv_bfloat16 eh = __float2bfloat16(e);
            __nv_bfloat16 oh2 = __float2bfloat16(o);
            __nv_bfloat16 el = __float2bfloat16(e - __bfloat162float(eh));
            __nv_bfloat16 ol2 = __float2bfloat16(o - __bfloat162float(oh2));
            size_t idx = ((size_t)(b*SS + srow))*DD + h*64 + nt*8 + t4*2;
            *(__nv_bfloat162*)(Oh + idx) = __nv_bfloat162(eh, oh2);
            *(__nv_bfloat162*)(Ol + idx) = __nv_bfloat162(el, ol2);
        }
    }
}

// ---------------------------------------------------------------------------
extern "C" void kernel_launch(void* const* d_in, const int* in_sizes, int n_in,
                              void* d_out, int out_size) {
    const float* x  = (const float*)d_in[0];
    const float* wq = (const float*)d_in[1];
    const float* wk = (const float*)d_in[2];
    const float* wv = (const float*)d_in[3];
    const float* wo = (const float*)d_in[4];
    float* out = (float*)d_out;

    __nv_bfloat16 *pqh, *pkh, *pvh, *pvl, *pxh, *pxl, *pwh, *pwl, *pah, *pal;
    cudaGetSymbolAddress((void**)&pqh, g_qh);
    cudaGetSymbolAddress((void**)&pkh, g_kh);
    cudaGetSymbolAddress((void**)&pvh, g_vh);
    cudaGetSymbolAddress((void**)&pvl, g_vl);
    cudaGetSymbolAddress((void**)&pxh, g_xhi);
    cudaGetSymbolAddress((void**)&pxl, g_xlo);
    cudaGetSymbolAddress((void**)&pwh, g_whi);
    cudaGetSymbolAddress((void**)&pwl, g_wlo);
    cudaGetSymbolAddress((void**)&pah, g_ahi);
    cudaGetSymbolAddress((void**)&pal, g_alo);

    rope_table_kernel<<<64, 1024>>>();

    const int nx = MM * DD;      // 4M
    const int nw = DD * DD;      // 1M
    split_kernel<<<nx/1024, 256>>>(x,  pxh, pxl, nx);
    split_kernel<<<nw/1024, 256>>>(wq, pwh + 0*nw, pwl + 0*nw, nw);
    split_kernel<<<nw/1024, 256>>>(wk, pwh + 1*nw, pwl + 1*nw, nw);
    split_kernel<<<nw/1024, 256>>>(wv, pwh + 2*nw, pwl + 2*nw, nw);
    split_kernel<<<nw/1024, 256>>>(wo, pwh + 3*nw, pwl + 3*nw, nw);

    dim3 gGrid(8, 32);   // N/128 x M/128
    tcgemm_kernel<<<gGrid, 256>>>(pxh, pxl, pwh + 0*nw, pwl + 0*nw,
                                  nullptr, pqh, nullptr, 2);   // Q: rope+scale
    tcgemm_kernel<<<gGrid, 256>>>(pxh, pxl, pwh + 1*nw, pwl + 1*nw,
                                  nullptr, pkh, nullptr, 3);   // K: rope
    tcgemm_kernel<<<gGrid, 256>>>(pxh, pxl, pwh + 2*nw, pwl + 2*nw,
                                  nullptr, pvh, pvl, 1);       // V: hi/lo

    flash_tc_kernel<<<dim3(32, 32), 128>>>(pqh, pkh, pvh, pvl, pah, pal);

    tcgemm_kernel<<<gGrid, 256>>>(pah, pal, pwh + 3*nw, pwl + 3*nw,
                                  out, nullptr, nullptr, 0);   // output proj
}

// round 13
// speedup vs baseline: 3.1536x; 1.0981x over previous
#include <cuda_runtime.h>
#include <cuda_bf16.h>
#include <cstdint>
#include <math.h>

// Problem constants
#define BB 2
#define SS 2048
#define DD 1024
#define HH 16
#define DK 64
#define MM (BB*SS)   // 4096 rows

// Scratch (allocation-free rule: __device__ globals)
__device__ __nv_bfloat16 g_qh[BB*HH*SS*DK];   // [b,h,s,dk] bf16 (rope, x0.125)
__device__ __nv_bfloat16 g_kh[BB*HH*SS*DK];   // [b,h,s,dk] bf16 (rope)
__device__ __nv_bfloat16 g_vh[BB*HH*SS*DK];   // [b,h,s,dk] bf16 hi
__device__ __nv_bfloat16 g_vl[BB*HH*SS*DK];   // [b,h,s,dk] bf16 lo
__device__ float g_cos[SS*(DK/2)];
__device__ float g_sin[SS*(DK/2)];
// bf16 split buffers for GEMM inputs
__device__ __nv_bfloat16 g_xhi[MM*DD], g_xlo[MM*DD];
__device__ __nv_bfloat16 g_whi[4*DD*DD], g_wlo[4*DD*DD];   // q,k,v,o
__device__ __nv_bfloat16 g_ahi[MM*DD], g_alo[MM*DD];       // attn out hi/lo

// ---------------------------------------------------------------------------
// Warp-level tensor-core + cp.async primitives (portable PTX, compute_103)
// ---------------------------------------------------------------------------
__device__ __forceinline__ uint32_t smem_u32(const void* p) {
    uint32_t a;
    asm("{ .reg .u64 t; cvta.to.shared.u64 t, %1; cvt.u32.u64 %0, t; }"
        : "=r"(a) : "l"(p));
    return a;
}
__device__ __forceinline__ void ldsm_x4(uint32_t& r0, uint32_t& r1,
                                        uint32_t& r2, uint32_t& r3,
                                        uint32_t addr) {
    asm volatile("ldmatrix.sync.aligned.m8n8.x4.shared.b16 {%0,%1,%2,%3}, [%4];"
                 : "=r"(r0), "=r"(r1), "=r"(r2), "=r"(r3) : "r"(addr));
}
__device__ __forceinline__ void ldsm_x4t(uint32_t& r0, uint32_t& r1,
                                         uint32_t& r2, uint32_t& r3,
                                         uint32_t addr) {
    asm volatile("ldmatrix.sync.aligned.m8n8.x4.trans.shared.b16 {%0,%1,%2,%3}, [%4];"
                 : "=r"(r0), "=r"(r1), "=r"(r2), "=r"(r3) : "r"(addr));
}
__device__ __forceinline__ void mma_bf16(float* d, uint32_t a0, uint32_t a1,
                                         uint32_t a2, uint32_t a3,
                                         uint32_t b0, uint32_t b1) {
    asm volatile(
        "mma.sync.aligned.m16n8k16.row.col.f32.bf16.bf16.f32 "
        "{%0,%1,%2,%3}, {%4,%5,%6,%7}, {%8,%9}, {%0,%1,%2,%3};"
        : "+f"(d[0]), "+f"(d[1]), "+f"(d[2]), "+f"(d[3])
        : "r"(a0), "r"(a1), "r"(a2), "r"(a3), "r"(b0), "r"(b1));
}
__device__ __forceinline__ void cp16(uint32_t saddr, const void* gaddr) {
    asm volatile("cp.async.cg.shared.global [%0], [%1], 16;"
                 :: "r"(saddr), "l"(gaddr) : "memory");
}
#define CP_COMMIT() asm volatile("cp.async.commit_group;" ::: "memory")
#define CP_WAIT1()  asm volatile("cp.async.wait_group 1;" ::: "memory")
#define CP_WAIT0()  asm volatile("cp.async.wait_group 0;" ::: "memory")
__device__ __forceinline__ uint32_t swz128(uint32_t o) { return o ^ ((o >> 3) & 0x70); }
__device__ __forceinline__ uint32_t pack_bf2(float a, float b) {
    __nv_bfloat162 t(__float2bfloat16(a), __float2bfloat16(b));
    return *(uint32_t*)&t;
}

// ---------------------------------------------------------------------------
// RoPE table
// ---------------------------------------------------------------------------
__global__ void rope_table_kernel() {
    int idx = blockIdx.x * blockDim.x + threadIdx.x;
    if (idx >= SS*(DK/2)) return;
    int s = idx >> 5;
    int j = idx & 31;
    double inv = exp(-(double)(2*j) / 64.0 * 9.210340371976184);
    float ang = (float)((double)s * inv);
    g_cos[idx] = cosf(ang);
    g_sin[idx] = sinf(ang);
}

// ---------------------------------------------------------------------------
// fp32 -> bf16 hi/lo split
// ---------------------------------------------------------------------------
__global__ void split_kernel(const float* __restrict__ src,
                             __nv_bfloat16* __restrict__ hi,
                             __nv_bfloat16* __restrict__ lo, int n) {
    int i = (blockIdx.x * blockDim.x + threadIdx.x) * 4;
    if (i >= n) return;
    float4 v = *(const float4*)(src + i);
    __nv_bfloat16 h0 = __float2bfloat16(v.x), h1 = __float2bfloat16(v.y);
    __nv_bfloat16 h2 = __float2bfloat16(v.z), h3 = __float2bfloat16(v.w);
    __nv_bfloat16 l0 = __float2bfloat16(v.x - __bfloat162float(h0));
    __nv_bfloat16 l1 = __float2bfloat16(v.y - __bfloat162float(h1));
    __nv_bfloat16 l2 = __float2bfloat16(v.z - __bfloat162float(h2));
    __nv_bfloat16 l3 = __float2bfloat16(v.w - __bfloat162float(h3));
    *(__nv_bfloat162*)(hi + i)     = __nv_bfloat162(h0, h1);
    *(__nv_bfloat162*)(hi + i + 2) = __nv_bfloat162(h2, h3);
    *(__nv_bfloat162*)(lo + i)     = __nv_bfloat162(l0, l1);
    *(__nv_bfloat162*)(lo + i + 2) = __nv_bfloat162(l2, l3);
}

// ---------------------------------------------------------------------------
// Tensor-core GEMM, C[m][n] = sum_k A[m][k]*W[n][k], fp32 via 2-way bf16
// split. Single K-loop (16 chunks of 64): per chunk load Ahi/Alo/Bhi/Blo
// and issue hi*hi + lo*hi + hi*lo on resident tiles. cp.async double-buffer.
// CTA 128x128, 8 warps each 64x32.
// mode 0: fp32 row-major to fout
// mode 1: V -> bf16 hi/lo [b,h,s,dk]
// mode 2: Q -> rope, x0.125, bf16 [b,h,s,dk]
// mode 3: K -> rope, bf16 [b,h,s,dk]
// ---------------------------------------------------------------------------
#define GBUF 65536u    // per-buffer: Ahi 16K | Alo 16K | Bhi 16K | Blo 16K

__global__ __launch_bounds__(256) void tcgemm_kernel(
    const __nv_bfloat16* __restrict__ Ahi, const __nv_bfloat16* __restrict__ Alo,
    const __nv_bfloat16* __restrict__ Bhi, const __nv_bfloat16* __restrict__ Blo,
    float* __restrict__ fout, __nv_bfloat16* __restrict__ oh,
    __nv_bfloat16* __restrict__ ol, int mode)
{
    extern __shared__ __align__(1024) char smem[];
    const uint32_t sb = smem_u32(smem);

    const int tid  = threadIdx.x;
    const int wid  = tid >> 5, lane = tid & 31;
    const int mBase = blockIdx.y * 128;
    const int nBase = blockIdx.x * 128;
    const int warp_m = wid >> 2;
    const int warp_n = wid & 3;

    float acc[4][4][4];
    #pragma unroll
    for (int i = 0; i < 4; i++)
        #pragma unroll
        for (int j = 0; j < 4; j++)
            #pragma unroll
            for (int q = 0; q < 4; q++) acc[i][j][q] = 0.f;

    const int lrow = tid >> 3;
    const int lseg = tid & 7;
    const int aRow = lane & 15;
    const int aSeg = lane >> 4;
    const int bRow = (lane & 7) + ((lane & 16) ? 8 : 0);
    const int bSeg = (lane >> 3) & 1;

    auto prefetch = [&](int c) {
        const int k0 = c * 64;
        const uint32_t base = sb + (uint32_t)(c & 1) * GBUF;
        #pragma unroll
        for (int i = 0; i < 4; i++) {
            int row = lrow + i * 32;
            uint32_t so = swz128((uint32_t)(row * 128 + lseg * 16));
            size_t ga = (size_t)(mBase + row) * DD + k0 + lseg * 8;
            size_t gb = (size_t)(nBase + row) * DD + k0 + lseg * 8;
            cp16(base + so,          Ahi + ga);
            cp16(base + 16384 + so,  Alo + ga);
            cp16(base + 32768 + so,  Bhi + gb);
            cp16(base + 49152 + so,  Blo + gb);
        }
        CP_COMMIT();
    };

    prefetch(0);
    for (int c = 0; c < 16; c++) {
        if (c + 1 < 16) { prefetch(c + 1); CP_WAIT1(); }
        else            { CP_WAIT0(); }
        __syncthreads();

        const uint32_t bA  = sb + (uint32_t)(c & 1) * GBUF;
        const uint32_t bAl = bA + 16384;
        const uint32_t bB  = bA + 32768;
        const uint32_t bBl = bA + 49152;

        #pragma unroll
        for (int ks = 0; ks < 4; ks++) {
            uint32_t ah[4][4], al[4][4], bh[2][4], bl[2][4];
            #pragma unroll
            for (int mt = 0; mt < 4; mt++) {
                uint32_t off = swz128((uint32_t)((warp_m*64 + mt*16 + aRow)*128
                                                  + ks*32 + aSeg*16));
                ldsm_x4(ah[mt][0], ah[mt][1], ah[mt][2], ah[mt][3], bA  + off);
                ldsm_x4(al[mt][0], al[mt][1], al[mt][2], al[mt][3], bAl + off);
            }
            #pragma unroll
            for (int nt2 = 0; nt2 < 2; nt2++) {
                uint32_t off = swz128((uint32_t)((warp_n*32 + nt2*16 + bRow)*128
                                                  + ks*32 + bSeg*16));
                ldsm_x4(bh[nt2][0], bh[nt2][1], bh[nt2][2], bh[nt2][3], bB  + off);
                ldsm_x4(bl[nt2][0], bl[nt2][1], bl[nt2][2], bl[nt2][3], bBl + off);
            }
            #pragma unroll
            for (int mt = 0; mt < 4; mt++) {
                #pragma unroll
                for (int nt = 0; nt < 4; nt++) {
                    uint32_t b0 = (nt < 2) ? bh[0][(nt&1)*2]   : bh[1][(nt&1)*2];
                    uint32_t b1 = (nt < 2) ? bh[0][(nt&1)*2+1] : bh[1][(nt&1)*2+1];
                    uint32_t c0 = (nt < 2) ? bl[0][(nt&1)*2]   : bl[1][(nt&1)*2];
                    uint32_t c1 = (nt < 2) ? bl[0][(nt&1)*2+1] : bl[1][(nt&1)*2+1];
                    mma_bf16(acc[mt][nt], ah[mt][0],ah[mt][1],ah[mt][2],ah[mt][3], b0, b1);
                    mma_bf16(acc[mt][nt], al[mt][0],al[mt][1],al[mt][2],al[mt][3], b0, b1);
                    mma_bf16(acc[mt][nt], ah[mt][0],ah[mt][1],ah[mt][2],ah[mt][3], c0, c1);
                }
            }
        }
        __syncthreads();
    }

    const int rQuad = lane >> 2;
    const int cPair = (lane & 3) * 2;

    #pragma unroll
    for (int mt = 0; mt < 4; mt++) {
        #pragma unroll
        for (int nt = 0; nt < 4; nt++) {
            const int col = nBase + warp_n*32 + nt*8 + cPair;
            #pragma unroll
            for (int hrow = 0; hrow < 2; hrow++) {
                const int row = mBase + warp_m*64 + mt*16 + rQuad + hrow*8;
                float e = acc[mt][nt][hrow*2 + 0];
                float o = acc[mt][nt][hrow*2 + 1];
                if (mode == 0) {
                    *(float2*)(fout + (size_t)row * DD + col) = make_float2(e, o);
                } else {
                    const int b = row >> 11, s = row & 2047;
                    const int h = col >> 6, dk = col & 63;
                    if (mode >= 2) {   // RoPE
                        float cc = g_cos[s*32 + (dk >> 1)];
                        float sn = g_sin[s*32 + (dk >> 1)];
                        float ev = e * cc - o * sn;
                        float od = o * cc + e * sn;
                        e = ev; o = od;
                        if (mode == 2) { e *= 0.125f; o *= 0.125f; }
                    }
                    size_t idx = ((size_t)((b*HH + h)*SS + s)) * DK + dk;
                    __nv_bfloat16 eh = __float2bfloat16(e);
                    __nv_bfloat16 oh2 = __float2bfloat16(o);
                    *(__nv_bfloat162*)(oh + idx) = __nv_bfloat162(eh, oh2);
                    if (mode == 1) {
                        __nv_bfloat16 el = __float2bfloat16(e - __bfloat162float(eh));
                        __nv_bfloat16 ol2 = __float2bfloat16(o - __bfloat162float(oh2));
                        *(__nv_bfloat162*)(ol + idx) = __nv_bfloat162(el, ol2);
                    }
                }
            }
        }
    }
}

// ---------------------------------------------------------------------------
// Tensor-core flash attention, causal, cp.async double-buffered K/V.
// 1 CTA = (b,h) x 64 queries; 4 warps x 16 query rows; 64-key tiles.
// QK^T: plain bf16. PV: 2-way split. Output bf16 hi/lo in [b,s,D].
// smem: Q 8K | buf0 (K 8K | Vh 8K | Vl 8K) | buf1 (...)  = 56KB dynamic
// ---------------------------------------------------------------------------
#define FBUF 24576u

__global__ __launch_bounds__(128) void flash_tc_kernel(
    const __nv_bfloat16* __restrict__ Qh, const __nv_bfloat16* __restrict__ Kh,
    const __nv_bfloat16* __restrict__ Vh, const __nv_bfloat16* __restrict__ Vl,
    __nv_bfloat16* __restrict__ Oh, __nv_bfloat16* __restrict__ Ol)
{
    extern __shared__ __align__(1024) char fsm[];
    const uint32_t sQ = smem_u32(fsm);

    const int qb  = gridDim.x - 1 - blockIdx.x;   // big tiles first
    const int bh  = blockIdx.y;
    const int tid = threadIdx.x;
    const int warp = tid >> 5, lane = tid & 31;
    const int quad = lane >> 2, t4 = lane & 3;

    const __nv_bfloat16* Qg  = Qh + ((size_t)bh*SS + qb*64)*DK;
    const __nv_bfloat16* Kg  = Kh + (size_t)bh*SS*DK;
    const __nv_bfloat16* Vhg = Vh + (size_t)bh*SS*DK;
    const __nv_bfloat16* Vlg = Vl + (size_t)bh*SS*DK;

    const int fr = tid >> 1, fs0 = (tid & 1) * 4;

    auto prefetch_kv = [&](int kb) {
        const uint32_t base = sQ + 8192 + (uint32_t)(kb & 1) * FBUF;
        size_t gro = (size_t)(kb*64 + fr) * DK;
        #pragma unroll
        for (int u = 0; u < 4; u++) {
            uint32_t so = swz128((uint32_t)(fr*128 + (fs0+u)*16));
            cp16(base + so,          Kg  + gro + (fs0+u)*8);
            cp16(base + 8192 + so,   Vhg + gro + (fs0+u)*8);
            cp16(base + 16384 + so,  Vlg + gro + (fs0+u)*8);
        }
        CP_COMMIT();
    };

    // Load Q tile (64 rows x 128B), swizzled
    {
        #pragma unroll
        for (int u = 0; u < 4; u++) {
            uint32_t so = swz128((uint32_t)(fr*128 + (fs0+u)*16));
            *(uint4*)(fsm + so) = *(const uint4*)(Qg + (size_t)fr*DK + (fs0+u)*8);
        }
    }
    prefetch_kv(0);
    __syncthreads();

    // Hoist Q a-frags
    uint32_t qf[4][4];
    {
        const int aRow = lane & 15, aSeg = lane >> 4;
        #pragma unroll
        for (int ks = 0; ks < 4; ks++) {
            uint32_t off = swz128((uint32_t)((warp*16 + aRow)*128 + ks*32 + aSeg*16));
            ldsm_x4(qf[ks][0], qf[ks][1], qf[ks][2], qf[ks][3], sQ + off);
        }
    }

    float m[2] = {-1e30f, -1e30f}, l[2] = {0.f, 0.f};
    float acc[8][4];
    #pragma unroll
    for (int nt = 0; nt < 8; nt++)
        #pragma unroll
        for (int q = 0; q < 4; q++) acc[nt][q] = 0.f;

    const int bRow = (lane & 7) + ((lane & 16) ? 8 : 0);
    const int bSeg = (lane >> 3) & 1;
    const int vmi = lane >> 3, vrow = lane & 7;

    for (int kb = 0; kb <= qb; kb++) {
        if (kb + 1 <= qb) { prefetch_kv(kb + 1); CP_WAIT1(); }
        else              { CP_WAIT0(); }
        __syncthreads();

        const uint32_t sK  = sQ + 8192 + (uint32_t)(kb & 1) * FBUF;
        const uint32_t sVh = sK + 8192;
        const uint32_t sVl = sK + 16384;

        // S = Q K^T (one bf16 pass)
        float s[8][4];
        #pragma unroll
        for (int nt = 0; nt < 8; nt++)
            #pragma unroll
            for (int q = 0; q < 4; q++) s[nt][q] = 0.f;
        #pragma unroll
        for (int ks = 0; ks < 4; ks++) {
            #pragma unroll
            for (int g = 0; g < 4; g++) {
                uint32_t k0, k1, k2, k3;
                uint32_t off = swz128((uint32_t)((g*16 + bRow)*128 + ks*32 + bSeg*16));
                ldsm_x4(k0, k1, k2, k3, sK + off);
                mma_bf16(s[g*2],   qf[ks][0],qf[ks][1],qf[ks][2],qf[ks][3], k0, k1);
                mma_bf16(s[g*2+1], qf[ks][0],qf[ks][1],qf[ks][2],qf[ks][3], k2, k3);
            }
        }

        if (kb == qb) {   // causal mask on diagonal tile
            #pragma unroll
            for (int nt = 0; nt < 8; nt++)
                #pragma unroll
                for (int e = 0; e < 4; e++) {
                    int qrow = warp*16 + quad + (e >> 1)*8;
                    int kcol = nt*8 + t4*2 + (e & 1);
                    if (kcol > qrow) s[nt][e] = -1e30f;
                }
        }

        // Online softmax
        float corr[2];
        #pragma unroll
        for (int hr = 0; hr < 2; hr++) {
            float mx = -1e30f;
            #pragma unroll
            for (int nt = 0; nt < 8; nt++)
                mx = fmaxf(mx, fmaxf(s[nt][hr*2], s[nt][hr*2+1]));
            mx = fmaxf(mx, __shfl_xor_sync(0xffffffffu, mx, 1));
            mx = fmaxf(mx, __shfl_xor_sync(0xffffffffu, mx, 2));
            float mn = fmaxf(m[hr], mx);
            corr[hr] = __expf(m[hr] - mn);
            m[hr] = mn;
            float sum = 0.f;
            #pragma unroll
            for (int nt = 0; nt < 8; nt++) {
                float p0 = __expf(s[nt][hr*2]   - mn);
                float p1 = __expf(s[nt][hr*2+1] - mn);
                s[nt][hr*2] = p0; s[nt][hr*2+1] = p1;
                sum += p0 + p1;
            }
            sum += __shfl_xor_sync(0xffffffffu, sum, 1);
            sum += __shfl_xor_sync(0xffffffffu, sum, 2);
            l[hr] = l[hr]*corr[hr] + sum;
        }
        #pragma unroll
        for (int nt = 0; nt < 8; nt++) {
            acc[nt][0] *= corr[0]; acc[nt][1] *= corr[0];
            acc[nt][2] *= corr[1]; acc[nt][3] *= corr[1];
        }

        // P -> bf16 hi/lo fragments
        uint32_t phi[8][2], plo[8][2];
        #pragma unroll
        for (int nt = 0; nt < 8; nt++) {
            float f0 = s[nt][0], f1 = s[nt][1], f2 = s[nt][2], f3 = s[nt][3];
            phi[nt][0] = pack_bf2(f0, f1);
            phi[nt][1] = pack_bf2(f2, f3);
            __nv_bfloat162 h0 = *(__nv_bfloat162*)&phi[nt][0];
            __nv_bfloat162 h1 = *(__nv_bfloat162*)&phi[nt][1];
            plo[nt][0] = pack_bf2(f0 - __bfloat162float(h0.x),
                                  f1 - __bfloat162float(h0.y));
            plo[nt][1] = pack_bf2(f2 - __bfloat162float(h1.x),
                                  f3 - __bfloat162float(h1.y));
        }

        // O += Phi*Vhi + Plo*Vhi + Phi*Vlo
        #pragma unroll
        for (int kt = 0; kt < 4; kt++) {
            uint32_t ah0 = phi[2*kt][0], ah1 = phi[2*kt][1];
            uint32_t ah2 = phi[2*kt+1][0], ah3 = phi[2*kt+1][1];
            uint32_t al0 = plo[2*kt][0], al1 = plo[2*kt][1];
            uint32_t al2 = plo[2*kt+1][0], al3 = plo[2*kt+1][1];
            #pragma unroll
            for (int g = 0; g < 4; g++) {
                uint32_t off = swz128((uint32_t)(
                    (kt*16 + (vmi & 1)*8 + vrow)*128 + (g*16 + (vmi >> 1)*8)*2));
                uint32_t vh0, vh1, vh2, vh3, vl0, vl1, vl2, vl3;
                ldsm_x4t(vh0, vh1, vh2, vh3, sVh + off);
                ldsm_x4t(vl0, vl1, vl2, vl3, sVl + off);
                mma_bf16(acc[g*2],   ah0,ah1,ah2,ah3, vh0, vh1);
                mma_bf16(acc[g*2+1], ah0,ah1,ah2,ah3, vh2, vh3);
                mma_bf16(acc[g*2],   al0,al1,al2,al3, vh0, vh1);
                mma_bf16(acc[g*2+1], al0,al1,al2,al3, vh2, vh3);
                mma_bf16(acc[g*2],   ah0,ah1,ah2,ah3, vl0, vl1);
                mma_bf16(acc[g*2+1], ah0,ah1,ah2,ah3, vl2, vl3);
            }
        }
        __syncthreads();
    }

    // Epilogue: O/l, write bf16 hi/lo in [b,s,D]
    const int b = bh >> 4, h = bh & 15;
    #pragma unroll
    for (int hr = 0; hr < 2; hr++) {
        float inv = 1.f / l[hr];
        int srow = qb*64 + warp*16 + quad + hr*8;
        #pragma unroll
        for (int nt = 0; nt < 8; nt++) {
            float e = acc[nt][hr*2]   * inv;
            float o = acc[nt][hr*2+1] * inv;
            __nv_bfloat16 eh = __float2bfloat16(e);
            __nv_bfloat16 oh2 = __float2bfloat16(o);
            __nv_bfloat16 el = __float2bfloat16(e - __bfloat162float(eh));
            __nv_bfloat16 ol2 = __float2bfloat16(o - __bfloat162float(oh2));
            size_t idx = ((size_t)(b*SS + srow))*DD + h*64 + nt*8 + t4*2;
            *(__nv_bfloat162*)(Oh + idx) = __nv_bfloat162(eh, oh2);
            *(__nv_bfloat162*)(Ol + idx) = __nv_bfloat162(el, ol2);
        }
    }
}

// ---------------------------------------------------------------------------
extern "C" void kernel_launch(void* const* d_in, const int* in_sizes, int n_in,
                              void* d_out, int out_size) {
    const float* x  = (const float*)d_in[0];
    const float* wq = (const float*)d_in[1];
    const float* wk = (const float*)d_in[2];
    const float* wv = (const float*)d_in[3];
    const float* wo = (const float*)d_in[4];
    float* out = (float*)d_out;

    __nv_bfloat16 *pqh, *pkh, *pvh, *pvl, *pxh, *pxl, *pwh, *pwl, *pah, *pal;
    cudaGetSymbolAddress((void**)&pqh, g_qh);
    cudaGetSymbolAddress((void**)&pkh, g_kh);
    cudaGetSymbolAddress((void**)&pvh, g_vh);
    cudaGetSymbolAddress((void**)&pvl, g_vl);
    cudaGetSymbolAddress((void**)&pxh, g_xhi);
    cudaGetSymbolAddress((void**)&pxl, g_xlo);
    cudaGetSymbolAddress((void**)&pwh, g_whi);
    cudaGetSymbolAddress((void**)&pwl, g_wlo);
    cudaGetSymbolAddress((void**)&pah, g_ahi);
    cudaGetSymbolAddress((void**)&pal, g_alo);

    cudaFuncSetAttribute(tcgemm_kernel,
                         cudaFuncAttributeMaxDynamicSharedMemorySize, 2*GBUF);
    cudaFuncSetAttribute(flash_tc_kernel,
                         cudaFuncAttributeMaxDynamicSharedMemorySize, 8192 + 2*FBUF);

    rope_table_kernel<<<64, 1024>>>();

    const int nx = MM * DD;      // 4M
    const int nw = DD * DD;      // 1M
    split_kernel<<<nx/1024, 256>>>(x,  pxh, pxl, nx);
    split_kernel<<<nw/1024, 256>>>(wq, pwh + 0*nw, pwl + 0*nw, nw);
    split_kernel<<<nw/1024, 256>>>(wk, pwh + 1*nw, pwl + 1*nw, nw);
    split_kernel<<<nw/1024, 256>>>(wv, pwh + 2*nw, pwl + 2*nw, nw);
    split_kernel<<<nw/1024, 256>>>(wo, pwh + 3*nw, pwl + 3*nw, nw);

    dim3 gGrid(8, 32);   // N/128 x M/128
    tcgemm_kernel<<<gGrid, 256, 2*GBUF>>>(pxh, pxl, pwh + 0*nw, pwl + 0*nw,
                                          nullptr, pqh, nullptr, 2);   // Q
    tcgemm_kernel<<<gGrid, 256, 2*GBUF>>>(pxh, pxl, pwh + 1*nw, pwl + 1*nw,
                                          nullptr, pkh, nullptr, 3);   // K
    tcgemm_kernel<<<gGrid, 256, 2*GBUF>>>(pxh, pxl, pwh + 2*nw, pwl + 2*nw,
                                          nullptr, pvh, pvl, 1);       // V

    flash_tc_kernel<<<dim3(32, 32), 128, 8192 + 2*FBUF>>>(pqh, pkh, pvh, pvl,
                                                          pah, pal);

    tcgemm_kernel<<<gGrid, 256, 2*GBUF>>>(pah, pal, pwh + 3*nw, pwl + 3*nw,
                                          out, nullptr, nullptr, 0);   // out proj
}

// round 15
// speedup vs baseline: 3.2328x; 1.0251x over previous
#include <cuda_runtime.h>
#include <cuda_bf16.h>
#include <cstdint>
#include <math.h>

// Problem constants
#define BB 2
#define SS 2048
#define DD 1024
#define HH 16
#define DK 64
#define MM (BB*SS)   // 4096 rows

// Scratch (allocation-free rule: __device__ globals)
__device__ __nv_bfloat16 g_qh[BB*HH*SS*DK];   // [b,h,s,dk] bf16 (rope, x0.125)
__device__ __nv_bfloat16 g_kh[BB*HH*SS*DK];   // [b,h,s,dk] bf16 (rope)
__device__ __nv_bfloat16 g_vh[BB*HH*SS*DK];   // [b,h,s,dk] bf16 hi
__device__ __nv_bfloat16 g_vl[BB*HH*SS*DK];   // [b,h,s,dk] bf16 lo
__device__ float g_cos[SS*(DK/2)];
__device__ float g_sin[SS*(DK/2)];
// bf16 split buffers for GEMM inputs
__device__ __nv_bfloat16 g_xhi[MM*DD], g_xlo[MM*DD];
__device__ __nv_bfloat16 g_whi[4*DD*DD], g_wlo[4*DD*DD];   // q,k,v,o
__device__ __nv_bfloat16 g_ahi[MM*DD], g_alo[MM*DD];       // attn out hi/lo

// ---------------------------------------------------------------------------
// Warp-level tensor-core + cp.async primitives (portable PTX, compute_103)
// ---------------------------------------------------------------------------
__device__ __forceinline__ uint32_t smem_u32(const void* p) {
    uint32_t a;
    asm("{ .reg .u64 t; cvta.to.shared.u64 t, %1; cvt.u32.u64 %0, t; }"
        : "=r"(a) : "l"(p));
    return a;
}
__device__ __forceinline__ void ldsm_x4(uint32_t& r0, uint32_t& r1,
                                        uint32_t& r2, uint32_t& r3,
                                        uint32_t addr) {
    asm volatile("ldmatrix.sync.aligned.m8n8.x4.shared.b16 {%0,%1,%2,%3}, [%4];"
                 : "=r"(r0), "=r"(r1), "=r"(r2), "=r"(r3) : "r"(addr));
}
__device__ __forceinline__ void ldsm_x4t(uint32_t& r0, uint32_t& r1,
                                         uint32_t& r2, uint32_t& r3,
                                         uint32_t addr) {
    asm volatile("ldmatrix.sync.aligned.m8n8.x4.trans.shared.b16 {%0,%1,%2,%3}, [%4];"
                 : "=r"(r0), "=r"(r1), "=r"(r2), "=r"(r3) : "r"(addr));
}
__device__ __forceinline__ void mma_bf16(float* d, uint32_t a0, uint32_t a1,
                                         uint32_t a2, uint32_t a3,
                                         uint32_t b0, uint32_t b1) {
    asm volatile(
        "mma.sync.aligned.m16n8k16.row.col.f32.bf16.bf16.f32 "
        "{%0,%1,%2,%3}, {%4,%5,%6,%7}, {%8,%9}, {%0,%1,%2,%3};"
        : "+f"(d[0]), "+f"(d[1]), "+f"(d[2]), "+f"(d[3])
        : "r"(a0), "r"(a1), "r"(a2), "r"(a3), "r"(b0), "r"(b1));
}
__device__ __forceinline__ void cp16(uint32_t saddr, const void* gaddr) {
    asm volatile("cp.async.cg.shared.global [%0], [%1], 16;"
                 :: "r"(saddr), "l"(gaddr) : "memory");
}
#define CP_COMMIT() asm volatile("cp.async.commit_group;" ::: "memory")
#define CP_WAIT1()  asm volatile("cp.async.wait_group 1;" ::: "memory")
#define CP_WAIT0()  asm volatile("cp.async.wait_group 0;" ::: "memory")
__device__ __forceinline__ uint32_t swz128(uint32_t o) { return o ^ ((o >> 3) & 0x70); }
__device__ __forceinline__ uint32_t pack_bf2(float a, float b) {
    __nv_bfloat162 t(__float2bfloat16(a), __float2bfloat16(b));
    return *(uint32_t*)&t;
}

// ---------------------------------------------------------------------------
// RoPE table
// ---------------------------------------------------------------------------
__global__ void rope_table_kernel() {
    int idx = blockIdx.x * blockDim.x + threadIdx.x;
    if (idx >= SS*(DK/2)) return;
    int s = idx >> 5;
    int j = idx & 31;
    double inv = exp(-(double)(2*j) / 64.0 * 9.210340371976184);
    float ang = (float)((double)s * inv);
    g_cos[idx] = cosf(ang);
    g_sin[idx] = sinf(ang);
}

// ---------------------------------------------------------------------------
// Fused fp32 -> bf16 hi/lo split for x + all 4 weights in ONE launch.
// Blocks [0, 4096)           -> x      (4M elems) -> g_xhi/g_xlo
// Blocks [4096 + i*1024, ..) -> w_i    (1M elems) -> g_whi/g_wlo + i*1M
// 256 threads x 4 elems = 1024 elems per block.
// ---------------------------------------------------------------------------
__global__ __launch_bounds__(256) void split_all_kernel(
    const float* __restrict__ x,  const float* __restrict__ wq,
    const float* __restrict__ wk, const float* __restrict__ wv,
    const float* __restrict__ wo)
{
    const int bid = blockIdx.x;
    const float* src;
    __nv_bfloat16 *hi, *lo;
    int off;
    if (bid < 4096) {
        src = x; hi = g_xhi; lo = g_xlo;
        off = bid * 1024;
    } else {
        int w = (bid - 4096) >> 10;          // 0..3
        int lb = (bid - 4096) & 1023;
        src = (w == 0) ? wq : (w == 1) ? wk : (w == 2) ? wv : wo;
        hi = g_whi + (size_t)w * DD * DD;
        lo = g_wlo + (size_t)w * DD * DD;
        off = lb * 1024;
    }
    int i = off + threadIdx.x * 4;
    float4 v = *(const float4*)(src + i);
    __nv_bfloat16 h0 = __float2bfloat16(v.x), h1 = __float2bfloat16(v.y);
    __nv_bfloat16 h2 = __float2bfloat16(v.z), h3 = __float2bfloat16(v.w);
    __nv_bfloat16 l0 = __float2bfloat16(v.x - __bfloat162float(h0));
    __nv_bfloat16 l1 = __float2bfloat16(v.y - __bfloat162float(h1));
    __nv_bfloat16 l2 = __float2bfloat16(v.z - __bfloat162float(h2));
    __nv_bfloat16 l3 = __float2bfloat16(v.w - __bfloat162float(h3));
    *(__nv_bfloat162*)(hi + i)     = __nv_bfloat162(h0, h1);
    *(__nv_bfloat162*)(hi + i + 2) = __nv_bfloat162(h2, h3);
    *(__nv_bfloat162*)(lo + i)     = __nv_bfloat162(l0, l1);
    *(__nv_bfloat162*)(lo + i + 2) = __nv_bfloat162(l2, l3);
}

// ---------------------------------------------------------------------------
// fp32 -> bf16 hi/lo split (single tensor; used for attn output)
// ---------------------------------------------------------------------------
__global__ void split_kernel(const float* __restrict__ src,
                             __nv_bfloat16* __restrict__ hi,
                             __nv_bfloat16* __restrict__ lo, int n) {
    int i = (blockIdx.x * blockDim.x + threadIdx.x) * 4;
    if (i >= n) return;
    float4 v = *(const float4*)(src + i);
    __nv_bfloat16 h0 = __float2bfloat16(v.x), h1 = __float2bfloat16(v.y);
    __nv_bfloat16 h2 = __float2bfloat16(v.z), h3 = __float2bfloat16(v.w);
    __nv_bfloat16 l0 = __float2bfloat16(v.x - __bfloat162float(h0));
    __nv_bfloat16 l1 = __float2bfloat16(v.y - __bfloat162float(h1));
    __nv_bfloat16 l2 = __float2bfloat16(v.z - __bfloat162float(h2));
    __nv_bfloat16 l3 = __float2bfloat16(v.w - __bfloat162float(h3));
    *(__nv_bfloat162*)(hi + i)     = __nv_bfloat162(h0, h1);
    *(__nv_bfloat162*)(hi + i + 2) = __nv_bfloat162(h2, h3);
    *(__nv_bfloat162*)(lo + i)     = __nv_bfloat162(l0, l1);
    *(__nv_bfloat162*)(lo + i + 2) = __nv_bfloat162(l2, l3);
}

// ---------------------------------------------------------------------------
// Tensor-core GEMM, C[m][n] = sum_k A[m][k]*W[n][k], fp32 via 2-way bf16
// split (hi*hi + lo*hi + hi*lo on resident tiles). cp.async double-buffer.
// CTA 128x128, 8 warps each 64x32, K-chunk 64.
// mode 0: fp32 row-major to fout
// mode 1: V -> bf16 hi/lo [b,h,s,dk]
// mode 2: Q -> rope, x0.125, bf16 [b,h,s,dk]
// mode 3: K -> rope, bf16 [b,h,s,dk]
// mode 9: fused QKV — blockIdx.z in {0,1,2} selects weight slice + output:
//         z=0 -> mode 2 (g_qh), z=1 -> mode 3 (g_kh), z=2 -> mode 1 (g_vh/g_vl)
// ---------------------------------------------------------------------------
#define GBUF 65536u    // per-buffer: Ahi 16K | Alo 16K | Bhi 16K | Blo 16K

__global__ __launch_bounds__(256, 1) void tcgemm_kernel(
    const __nv_bfloat16* __restrict__ Ahi, const __nv_bfloat16* __restrict__ Alo,
    const __nv_bfloat16* __restrict__ Bhi, const __nv_bfloat16* __restrict__ Blo,
    float* __restrict__ fout, __nv_bfloat16* __restrict__ oh,
    __nv_bfloat16* __restrict__ ol, int mode)
{
    extern __shared__ __align__(1024) char smem[];
    const uint32_t sb = smem_u32(smem);

    // Fused-QKV dispatch
    if (mode == 9) {
        const int z = blockIdx.z;
        const size_t nw = (size_t)DD * DD;
        Bhi = Bhi + z * nw;
        Blo = Blo + z * nw;
        if (z == 0)      { mode = 2; oh = g_qh; }
        else if (z == 1) { mode = 3; oh = g_kh; }
        else             { mode = 1; oh = g_vh; ol = g_vl; }
    }

    const int tid  = threadIdx.x;
    const int wid  = tid >> 5, lane = tid & 31;
    const int mBase = blockIdx.y * 128;
    const int nBase = blockIdx.x * 128;
    const int warp_m = wid >> 2;
    const int warp_n = wid & 3;

    float acc[4][4][4];
    #pragma unroll
    for (int i = 0; i < 4; i++)
        #pragma unroll
        for (int j = 0; j < 4; j++)
            #pragma unroll
            for (int q = 0; q < 4; q++) acc[i][j][q] = 0.f;

    const int lrow = tid >> 3;
    const int lseg = tid & 7;
    const int aRow = lane & 15;
    const int aSeg = lane >> 4;
    const int bRow = (lane & 7) + ((lane & 16) ? 8 : 0);
    const int bSeg = (lane >> 3) & 1;

    auto prefetch = [&](int c) {
        const int k0 = c * 64;
        const uint32_t base = sb + (uint32_t)(c & 1) * GBUF;
        #pragma unroll
        for (int i = 0; i < 4; i++) {
            int row = lrow + i * 32;
            uint32_t so = swz128((uint32_t)(row * 128 + lseg * 16));
            size_t ga = (size_t)(mBase + row) * DD + k0 + lseg * 8;
            size_t gb = (size_t)(nBase + row) * DD + k0 + lseg * 8;
            cp16(base + so,          Ahi + ga);
            cp16(base + 16384 + so,  Alo + ga);
            cp16(base + 32768 + so,  Bhi + gb);
            cp16(base + 49152 + so,  Blo + gb);
        }
        CP_COMMIT();
    };

    prefetch(0);
    for (int c = 0; c < 16; c++) {
        if (c + 1 < 16) { prefetch(c + 1); CP_WAIT1(); }
        else            { CP_WAIT0(); }
        __syncthreads();

        const uint32_t bA  = sb + (uint32_t)(c & 1) * GBUF;
        const uint32_t bAl = bA + 16384;
        const uint32_t bB  = bA + 32768;
        const uint32_t bBl = bA + 49152;

        #pragma unroll
        for (int ks = 0; ks < 4; ks++) {
            uint32_t ah[4][4], al[4][4], bh[2][4], bl[2][4];
            #pragma unroll
            for (int mt = 0; mt < 4; mt++) {
                uint32_t off = swz128((uint32_t)((warp_m*64 + mt*16 + aRow)*128
                                                  + ks*32 + aSeg*16));
                ldsm_x4(ah[mt][0], ah[mt][1], ah[mt][2], ah[mt][3], bA  + off);
                ldsm_x4(al[mt][0], al[mt][1], al[mt][2], al[mt][3], bAl + off);
            }
            #pragma unroll
            for (int nt2 = 0; nt2 < 2; nt2++) {
                uint32_t off = swz128((uint32_t)((warp_n*32 + nt2*16 + bRow)*128
                                                  + ks*32 + bSeg*16));
                ldsm_x4(bh[nt2][0], bh[nt2][1], bh[nt2][2], bh[nt2][3], bB  + off);
                ldsm_x4(bl[nt2][0], bl[nt2][1], bl[nt2][2], bl[nt2][3], bBl + off);
            }
            #pragma unroll
            for (int mt = 0; mt < 4; mt++) {
                #pragma unroll
                for (int nt = 0; nt < 4; nt++) {
                    uint32_t b0 = (nt < 2) ? bh[0][(nt&1)*2]   : bh[1][(nt&1)*2];
                    uint32_t b1 = (nt < 2) ? bh[0][(nt&1)*2+1] : bh[1][(nt&1)*2+1];
                    uint32_t c0 = (nt < 2) ? bl[0][(nt&1)*2]   : bl[1][(nt&1)*2];
                    uint32_t c1 = (nt < 2) ? bl[0][(nt&1)*2+1] : bl[1][(nt&1)*2+1];
                    mma_bf16(acc[mt][nt], ah[mt][0],ah[mt][1],ah[mt][2],ah[mt][3], b0, b1);
                    mma_bf16(acc[mt][nt], al[mt][0],al[mt][1],al[mt][2],al[mt][3], b0, b1);
                    mma_bf16(acc[mt][nt], ah[mt][0],ah[mt][1],ah[mt][2],ah[mt][3], c0, c1);
                }
            }
        }
        __syncthreads();
    }

    const int rQuad = lane >> 2;
    const int cPair = (lane & 3) * 2;

    #pragma unroll
    for (int mt = 0; mt < 4; mt++) {
        #pragma unroll
        for (int nt = 0; nt < 4; nt++) {
            const int col = nBase + warp_n*32 + nt*8 + cPair;
            #pragma unroll
            for (int hrow = 0; hrow < 2; hrow++) {
                const int row = mBase + warp_m*64 + mt*16 + rQuad + hrow*8;
                float e = acc[mt][nt][hrow*2 + 0];
                float o = acc[mt][nt][hrow*2 + 1];
                if (mode == 0) {
                    *(float2*)(fout + (size_t)row * DD + col) = make_float2(e, o);
                } else {
                    const int b = row >> 11, s = row & 2047;
                    const int h = col >> 6, dk = col & 63;
                    if (mode >= 2) {   // RoPE
                        float cc = g_cos[s*32 + (dk >> 1)];
                        float sn = g_sin[s*32 + (dk >> 1)];
                        float ev = e * cc - o * sn;
                        float od = o * cc + e * sn;
                        e = ev; o = od;
                        if (mode == 2) { e *= 0.125f; o *= 0.125f; }
                    }
                    size_t idx = ((size_t)((b*HH + h)*SS + s)) * DK + dk;
                    __nv_bfloat16 eh = __float2bfloat16(e);
                    __nv_bfloat16 oh2 = __float2bfloat16(o);
                    *(__nv_bfloat162*)(oh + idx) = __nv_bfloat162(eh, oh2);
                    if (mode == 1) {
                        __nv_bfloat16 el = __float2bfloat16(e - __bfloat162float(eh));
                        __nv_bfloat16 ol2 = __float2bfloat16(o - __bfloat162float(oh2));
                        *(__nv_bfloat162*)(ol + idx) = __nv_bfloat162(el, ol2);
                    }
                }
            }
        }
    }
}

// ---------------------------------------------------------------------------
// Tensor-core flash attention, causal, cp.async double-buffered K/V.
// 1 CTA = (b,h) x 64 queries; 4 warps x 16 query rows; 64-key tiles.
// QK^T: plain bf16. PV: 2-way split. Output bf16 hi/lo in [b,s,D].
// smem: Q 8K | buf0 (K 8K | Vh 8K | Vl 8K) | buf1 (...)  = 56KB dynamic
// ---------------------------------------------------------------------------
#define FBUF 24576u

__global__ __launch_bounds__(128) void flash_tc_kernel(
    const __nv_bfloat16* __restrict__ Qh, const __nv_bfloat16* __restrict__ Kh,
    const __nv_bfloat16* __restrict__ Vh, const __nv_bfloat16* __restrict__ Vl,
    __nv_bfloat16* __restrict__ Oh, __nv_bfloat16* __restrict__ Ol)
{
    extern __shared__ __align__(1024) char fsm[];
    const uint32_t sQ = smem_u32(fsm);

    const int qb  = gridDim.x - 1 - blockIdx.x;   // big tiles first
    const int bh  = blockIdx.y;
    const int tid = threadIdx.x;
    const int warp = tid >> 5, lane = tid & 31;
    const int quad = lane >> 2, t4 = lane & 3;

    const __nv_bfloat16* Qg  = Qh + ((size_t)bh*SS + qb*64)*DK;
    const __nv_bfloat16* Kg  = Kh + (size_t)bh*SS*DK;
    const __nv_bfloat16* Vhg = Vh + (size_t)bh*SS*DK;
    const __nv_bfloat16* Vlg = Vl + (size_t)bh*SS*DK;

    const int fr = tid >> 1, fs0 = (tid & 1) * 4;

    auto prefetch_kv = [&](int kb) {
        const uint32_t base = sQ + 8192 + (uint32_t)(kb & 1) * FBUF;
        size_t gro = (size_t)(kb*64 + fr) * DK;
        #pragma unroll
        for (int u = 0; u < 4; u++) {
            uint32_t so = swz128((uint32_t)(fr*128 + (fs0+u)*16));
            cp16(base + so,          Kg  + gro + (fs0+u)*8);
            cp16(base + 8192 + so,   Vhg + gro + (fs0+u)*8);
            cp16(base + 16384 + so,  Vlg + gro + (fs0+u)*8);
        }
        CP_COMMIT();
    };

    // Load Q tile (64 rows x 128B), swizzled
    {
        #pragma unroll
        for (int u = 0; u < 4; u++) {
            uint32_t so = swz128((uint32_t)(fr*128 + (fs0+u)*16));
            *(uint4*)(fsm + so) = *(const uint4*)(Qg + (size_t)fr*DK + (fs0+u)*8);
        }
    }
    prefetch_kv(0);
    __syncthreads();

    // Hoist Q a-frags
    uint32_t qf[4][4];
    {
        const int aRow = lane & 15, aSeg = lane >> 4;
        #pragma unroll
        for (int ks = 0; ks < 4; ks++) {
            uint32_t off = swz128((uint32_t)((warp*16 + aRow)*128 + ks*32 + aSeg*16));
            ldsm_x4(qf[ks][0], qf[ks][1], qf[ks][2], qf[ks][3], sQ + off);
        }
    }

    float m[2] = {-1e30f, -1e30f}, l[2] = {0.f, 0.f};
    float acc[8][4];
    #pragma unroll
    for (int nt = 0; nt < 8; nt++)
        #pragma unroll
        for (int q = 0; q < 4; q++) acc[nt][q] = 0.f;

    const int bRow = (lane & 7) + ((lane & 16) ? 8 : 0);
    const int bSeg = (lane >> 3) & 1;
    const int vmi = lane >> 3, vrow = lane & 7;

    for (int kb = 0; kb <= qb; kb++) {
        if (kb + 1 <= qb) { prefetch_kv(kb + 1); CP_WAIT1(); }
        else              { CP_WAIT0(); }
        __syncthreads();

        const uint32_t sK  = sQ + 8192 + (uint32_t)(kb & 1) * FBUF;
        const uint32_t sVh = sK + 8192;
        const uint32_t sVl = sK + 16384;

        // S = Q K^T (one bf16 pass)
        float s[8][4];
        #pragma unroll
        for (int nt = 0; nt < 8; nt++)
            #pragma unroll
            for (int q = 0; q < 4; q++) s[nt][q] = 0.f;
        #pragma unroll
        for (int ks = 0; ks < 4; ks++) {
            #pragma unroll
            for (int g = 0; g < 4; g++) {
                uint32_t k0, k1, k2, k3;
                uint32_t off = swz128((uint32_t)((g*16 + bRow)*128 + ks*32 + bSeg*16));
                ldsm_x4(k0, k1, k2, k3, sK + off);
                mma_bf16(s[g*2],   qf[ks][0],qf[ks][1],qf[ks][2],qf[ks][3], k0, k1);
                mma_bf16(s[g*2+1], qf[ks][0],qf[ks][1],qf[ks][2],qf[ks][3], k2, k3);
            }
        }

        if (kb == qb) {   // causal mask on diagonal tile
            #pragma unroll
            for (int nt = 0; nt < 8; nt++)
                #pragma unroll
                for (int e = 0; e < 4; e++) {
                    int qrow = warp*16 + quad + (e >> 1)*8;
                    int kcol = nt*8 + t4*2 + (e & 1);
                    if (kcol > qrow) s[nt][e] = -1e30f;
                }
        }

        // Online softmax
        float corr[2];
        #pragma unroll
        for (int hr = 0; hr < 2; hr++) {
            float mx = -1e30f;
            #pragma unroll
            for (int nt = 0; nt < 8; nt++)
                mx = fmaxf(mx, fmaxf(s[nt][hr*2], s[nt][hr*2+1]));
            mx = fmaxf(mx, __shfl_xor_sync(0xffffffffu, mx, 1));
            mx = fmaxf(mx, __shfl_xor_sync(0xffffffffu, mx, 2));
            float mn = fmaxf(m[hr], mx);
            corr[hr] = __expf(m[hr] - mn);
            m[hr] = mn;
            float sum = 0.f;
            #pragma unroll
            for (int nt = 0; nt < 8; nt++) {
                float p0 = __expf(s[nt][hr*2]   - mn);
                float p1 = __expf(s[nt][hr*2+1] - mn);
                s[nt][hr*2] = p0; s[nt][hr*2+1] = p1;
                sum += p0 + p1;
            }
            sum += __shfl_xor_sync(0xffffffffu, sum, 1);
            sum += __shfl_xor_sync(0xffffffffu, sum, 2);
            l[hr] = l[hr]*corr[hr] + sum;
        }
        #pragma unroll
        for (int nt = 0; nt < 8; nt++) {
            acc[nt][0] *= corr[0]; acc[nt][1] *= corr[0];
            acc[nt][2] *= corr[1]; acc[nt][3] *= corr[1];
        }

        // P -> bf16 hi/lo fragments
        uint32_t phi[8][2], plo[8][2];
        #pragma unroll
        for (int nt = 0; nt < 8; nt++) {
            float f0 = s[nt][0], f1 = s[nt][1], f2 = s[nt][2], f3 = s[nt][3];
            phi[nt][0] = pack_bf2(f0, f1);
            phi[nt][1] = pack_bf2(f2, f3);
            __nv_bfloat162 h0 = *(__nv_bfloat162*)&phi[nt][0];
            __nv_bfloat162 h1 = *(__nv_bfloat162*)&phi[nt][1];
            plo[nt][0] = pack_bf2(f0 - __bfloat162float(h0.x),
                                  f1 - __bfloat162float(h0.y));
            plo[nt][1] = pack_bf2(f2 - __bfloat162float(h1.x),
                                  f3 - __bfloat162float(h1.y));
        }

        // O += Phi*Vhi + Plo*Vhi + Phi*Vlo
        #pragma unroll
        for (int kt = 0; kt < 4; kt++) {
            uint32_t ah0 = phi[2*kt][0], ah1 = phi[2*kt][1];
            uint32_t ah2 = phi[2*kt+1][0], ah3 = phi[2*kt+1][1];
            uint32_t al0 = plo[2*kt][0], al1 = plo[2*kt][1];
            uint32_t al2 = plo[2*kt+1][0], al3 = plo[2*kt+1][1];
            #pragma unroll
            for (int g = 0; g < 4; g++) {
                uint32_t off = swz128((uint32_t)(
                    (kt*16 + (vmi & 1)*8 + vrow)*128 + (g*16 + (vmi >> 1)*8)*2));
                uint32_t vh0, vh1, vh2, vh3, vl0, vl1, vl2, vl3;
                ldsm_x4t(vh0, vh1, vh2, vh3, sVh + off);
                ldsm_x4t(vl0, vl1, vl2, vl3, sVl + off);
                mma_bf16(acc[g*2],   ah0,ah1,ah2,ah3, vh0, vh1);
                mma_bf16(acc[g*2+1], ah0,ah1,ah2,ah3, vh2, vh3);
                mma_bf16(acc[g*2],   al0,al1,al2,al3, vh0, vh1);
                mma_bf16(acc[g*2+1], al0,al1,al2,al3, vh2, vh3);
                mma_bf16(acc[g*2],   ah0,ah1,ah2,ah3, vl0, vl1);
                mma_bf16(acc[g*2+1], ah0,ah1,ah2,ah3, vl2, vl3);
            }
        }
        __syncthreads();
    }

    // Epilogue: O/l, write bf16 hi/lo in [b,s,D]
    const int b = bh >> 4, h = bh & 15;
    #pragma unroll
    for (int hr = 0; hr < 2; hr++) {
        float inv = 1.f / l[hr];
        int srow = qb*64 + warp*16 + quad + hr*8;
        #pragma unroll
        for (int nt = 0; nt < 8; nt++) {
            float e = acc[nt][hr*2]   * inv;
            float o = acc[nt][hr*2+1] * inv;
            __nv_bfloat16 eh = __float2bfloat16(e);
            __nv_bfloat16 oh2 = __float2bfloat16(o);
            __nv_bfloat16 el = __float2bfloat16(e - __bfloat162float(eh));
            __nv_bfloat16 ol2 = __float2bfloat16(o - __bfloat162float(oh2));
            size_t idx = ((size_t)(b*SS + srow))*DD + h*64 + nt*8 + t4*2;
            *(__nv_bfloat162*)(Oh + idx) = __nv_bfloat162(eh, oh2);
            *(__nv_bfloat162*)(Ol + idx) = __nv_bfloat162(el, ol2);
        }
    }
}

// ---------------------------------------------------------------------------
extern "C" void kernel_launch(void* const* d_in, const int* in_sizes, int n_in,
                              void* d_out, int out_size) {
    const float* x  = (const float*)d_in[0];
    const float* wq = (const float*)d_in[1];
    const float* wk = (const float*)d_in[2];
    const float* wv = (const float*)d_in[3];
    const float* wo = (const float*)d_in[4];
    float* out = (float*)d_out;

    __nv_bfloat16 *pqh, *pkh, *pvh, *pvl, *pxh, *pxl, *pwh, *pwl, *pah, *pal;
    cudaGetSymbolAddress((void**)&pqh, g_qh);
    cudaGetSymbolAddress((void**)&pkh, g_kh);
    cudaGetSymbolAddress((void**)&pvh, g_vh);
    cudaGetSymbolAddress((void**)&pvl, g_vl);
    cudaGetSymbolAddress((void**)&pxh, g_xhi);
    cudaGetSymbolAddress((void**)&pxl, g_xlo);
    cudaGetSymbolAddress((void**)&pwh, g_whi);
    cudaGetSymbolAddress((void**)&pwl, g_wlo);
    cudaGetSymbolAddress((void**)&pah, g_ahi);
    cudaGetSymbolAddress((void**)&pal, g_alo);

    cudaFuncSetAttribute(tcgemm_kernel,
                         cudaFuncAttributeMaxDynamicSharedMemorySize, 2*GBUF);
    cudaFuncSetAttribute(flash_tc_kernel,
                         cudaFuncAttributeMaxDynamicSharedMemorySize, 8192 + 2*FBUF);

    rope_table_kernel<<<64, 1024>>>();

    // One fused split: x (4096 blocks) + 4 weights (4 x 1024 blocks)
    split_all_kernel<<<8192, 256>>>(x, wq, wk, wv, wo);

    // Fused Q/K/V projection: grid.z selects weight + epilogue
    dim3 qkvGrid(8, 32, 3);
    tcgemm_kernel<<<qkvGrid, 256, 2*GBUF>>>(pxh, pxl, pwh, pwl,
                                            nullptr, nullptr, nullptr, 9);

    flash_tc_kernel<<<dim3(32, 32), 128, 8192 + 2*FBUF>>>(pqh, pkh, pvh, pvl,
                                                          pah, pal);

    const size_t nw = (size_t)DD * DD;
    dim3 gGrid(8, 32);
    tcgemm_kernel<<<gGrid, 256, 2*GBUF>>>(pah, pal, pwh + 3*nw, pwl + 3*nw,
                                          out, nullptr, nullptr, 0);   // out proj
}

// round 17
// speedup vs baseline: 3.7979x; 1.1748x over previous
#include <cuda_runtime.h>
#include <cuda_bf16.h>
#include <cuda_fp16.h>
#include <cstdint>
#include <math.h>

// Problem constants
#define BB 2
#define SS 2048
#define DD 1024
#define HH 16
#define DK 64
#define MM (BB*SS)   // 4096 rows

// Scratch (allocation-free rule: __device__ globals)
__device__ __nv_bfloat16 g_qh[BB*HH*SS*DK];   // [b,h,s,dk] bf16 (rope, x0.125)
__device__ __nv_bfloat16 g_kh[BB*HH*SS*DK];   // [b,h,s,dk] bf16 (rope)
__device__ __nv_bfloat16 g_vf[BB*HH*SS*DK];   // [b,h,s,dk] fp16 bits (V)
__device__ float g_cos[SS*(DK/2)];
__device__ float g_sin[SS*(DK/2)];
// bf16 split buffers for GEMM inputs
__device__ __nv_bfloat16 g_xhi[MM*DD], g_xlo[MM*DD];
__device__ __nv_bfloat16 g_whi[4*DD*DD], g_wlo[4*DD*DD];   // q,k,v,o
__device__ __nv_bfloat16 g_ahi[MM*DD], g_alo[MM*DD];       // attn out hi/lo

// ---------------------------------------------------------------------------
// Warp-level tensor-core + cp.async primitives (portable PTX, compute_103)
// ---------------------------------------------------------------------------
__device__ __forceinline__ uint32_t smem_u32(const void* p) {
    uint32_t a;
    asm("{ .reg .u64 t; cvta.to.shared.u64 t, %1; cvt.u32.u64 %0, t; }"
        : "=r"(a) : "l"(p));
    return a;
}
__device__ __forceinline__ void ldsm_x4(uint32_t& r0, uint32_t& r1,
                                        uint32_t& r2, uint32_t& r3,
                                        uint32_t addr) {
    asm volatile("ldmatrix.sync.aligned.m8n8.x4.shared.b16 {%0,%1,%2,%3}, [%4];"
                 : "=r"(r0), "=r"(r1), "=r"(r2), "=r"(r3) : "r"(addr));
}
__device__ __forceinline__ void ldsm_x4t(uint32_t& r0, uint32_t& r1,
                                         uint32_t& r2, uint32_t& r3,
                                         uint32_t addr) {
    asm volatile("ldmatrix.sync.aligned.m8n8.x4.trans.shared.b16 {%0,%1,%2,%3}, [%4];"
                 : "=r"(r0), "=r"(r1), "=r"(r2), "=r"(r3) : "r"(addr));
}
__device__ __forceinline__ void mma_bf16(float* d, uint32_t a0, uint32_t a1,
                                         uint32_t a2, uint32_t a3,
                                         uint32_t b0, uint32_t b1) {
    asm volatile(
        "mma.sync.aligned.m16n8k16.row.col.f32.bf16.bf16.f32 "
        "{%0,%1,%2,%3}, {%4,%5,%6,%7}, {%8,%9}, {%0,%1,%2,%3};"
        : "+f"(d[0]), "+f"(d[1]), "+f"(d[2]), "+f"(d[3])
        : "r"(a0), "r"(a1), "r"(a2), "r"(a3), "r"(b0), "r"(b1));
}
__device__ __forceinline__ void mma_f16(float* d, uint32_t a0, uint32_t a1,
                                        uint32_t a2, uint32_t a3,
                                        uint32_t b0, uint32_t b1) {
    asm volatile(
        "mma.sync.aligned.m16n8k16.row.col.f32.f16.f16.f32 "
        "{%0,%1,%2,%3}, {%4,%5,%6,%7}, {%8,%9}, {%0,%1,%2,%3};"
        : "+f"(d[0]), "+f"(d[1]), "+f"(d[2]), "+f"(d[3])
        : "r"(a0), "r"(a1), "r"(a2), "r"(a3), "r"(b0), "r"(b1));
}
__device__ __forceinline__ void cp16(uint32_t saddr, const void* gaddr) {
    asm volatile("cp.async.cg.shared.global [%0], [%1], 16;"
                 :: "r"(saddr), "l"(gaddr) : "memory");
}
#define CP_COMMIT() asm volatile("cp.async.commit_group;" ::: "memory")
#define CP_WAIT1()  asm volatile("cp.async.wait_group 1;" ::: "memory")
#define CP_WAIT0()  asm volatile("cp.async.wait_group 0;" ::: "memory")
__device__ __forceinline__ uint32_t swz128(uint32_t o) { return o ^ ((o >> 3) & 0x70); }
__device__ __forceinline__ uint32_t pack_h2(float a, float b) {
    __half2 t = __floats2half2_rn(a, b);
    return *(uint32_t*)&t;
}

// ---------------------------------------------------------------------------
// RoPE table
// ---------------------------------------------------------------------------
__global__ void rope_table_kernel() {
    int idx = blockIdx.x * blockDim.x + threadIdx.x;
    if (idx >= SS*(DK/2)) return;
    int s = idx >> 5;
    int j = idx & 31;
    double inv = exp(-(double)(2*j) / 64.0 * 9.210340371976184);
    float ang = (float)((double)s * inv);
    g_cos[idx] = cosf(ang);
    g_sin[idx] = sinf(ang);
}

// ---------------------------------------------------------------------------
// Fused fp32 -> bf16 hi/lo split for x + all 4 weights in ONE launch.
// ---------------------------------------------------------------------------
__global__ __launch_bounds__(256) void split_all_kernel(
    const float* __restrict__ x,  const float* __restrict__ wq,
    const float* __restrict__ wk, const float* __restrict__ wv,
    const float* __restrict__ wo)
{
    const int bid = blockIdx.x;
    const float* src;
    __nv_bfloat16 *hi, *lo;
    int off;
    if (bid < 4096) {
        src = x; hi = g_xhi; lo = g_xlo;
        off = bid * 1024;
    } else {
        int w = (bid - 4096) >> 10;          // 0..3
        int lb = (bid - 4096) & 1023;
        src = (w == 0) ? wq : (w == 1) ? wk : (w == 2) ? wv : wo;
        hi = g_whi + (size_t)w * DD * DD;
        lo = g_wlo + (size_t)w * DD * DD;
        off = lb * 1024;
    }
    int i = off + threadIdx.x * 4;
    float4 v = *(const float4*)(src + i);
    __nv_bfloat16 h0 = __float2bfloat16(v.x), h1 = __float2bfloat16(v.y);
    __nv_bfloat16 h2 = __float2bfloat16(v.z), h3 = __float2bfloat16(v.w);
    __nv_bfloat16 l0 = __float2bfloat16(v.x - __bfloat162float(h0));
    __nv_bfloat16 l1 = __float2bfloat16(v.y - __bfloat162float(h1));
    __nv_bfloat16 l2 = __float2bfloat16(v.z - __bfloat162float(h2));
    __nv_bfloat16 l3 = __float2bfloat16(v.w - __bfloat162float(h3));
    *(__nv_bfloat162*)(hi + i)     = __nv_bfloat162(h0, h1);
    *(__nv_bfloat162*)(hi + i + 2) = __nv_bfloat162(h2, h3);
    *(__nv_bfloat162*)(lo + i)     = __nv_bfloat162(l0, l1);
    *(__nv_bfloat162*)(lo + i + 2) = __nv_bfloat162(l2, l3);
}

// ---------------------------------------------------------------------------
// Tensor-core GEMM, C[m][n] = sum_k A[m][k]*W[n][k], fp32 via 2-way bf16
// split (hi*hi + lo*hi + hi*lo on resident tiles). cp.async double-buffer.
// CTA 128x128, 8 warps each 64x32, K-chunk 64.
// mode 0: fp32 row-major to fout
// mode 1: V -> fp16 [b,h,s,dk] (oh holds fp16 bits)
// mode 2: Q -> rope, x0.125, bf16 [b,h,s,dk]
// mode 3: K -> rope, bf16 [b,h,s,dk]
// mode 9: fused QKV — blockIdx.z selects weight slice + output
// ---------------------------------------------------------------------------
#define GBUF 65536u    // per-buffer: Ahi 16K | Alo 16K | Bhi 16K | Blo 16K

__global__ __launch_bounds__(256, 1) void tcgemm_kernel(
    const __nv_bfloat16* __restrict__ Ahi, const __nv_bfloat16* __restrict__ Alo,
    const __nv_bfloat16* __restrict__ Bhi, const __nv_bfloat16* __restrict__ Blo,
    float* __restrict__ fout, __nv_bfloat16* __restrict__ oh,
    __nv_bfloat16* __restrict__ ol, int mode)
{
    extern __shared__ __align__(1024) char smem[];
    const uint32_t sb = smem_u32(smem);

    // Fused-QKV dispatch
    if (mode == 9) {
        const int z = blockIdx.z;
        const size_t nw = (size_t)DD * DD;
        Bhi = Bhi + z * nw;
        Blo = Blo + z * nw;
        if (z == 0)      { mode = 2; oh = g_qh; }
        else if (z == 1) { mode = 3; oh = g_kh; }
        else             { mode = 1; oh = g_vf; }
    }

    const int tid  = threadIdx.x;
    const int wid  = tid >> 5, lane = tid & 31;
    const int mBase = blockIdx.y * 128;
    const int nBase = blockIdx.x * 128;
    const int warp_m = wid >> 2;
    const int warp_n = wid & 3;

    float acc[4][4][4];
    #pragma unroll
    for (int i = 0; i < 4; i++)
        #pragma unroll
        for (int j = 0; j < 4; j++)
            #pragma unroll
            for (int q = 0; q < 4; q++) acc[i][j][q] = 0.f;

    const int lrow = tid >> 3;
    const int lseg = tid & 7;
    const int aRow = lane & 15;
    const int aSeg = lane >> 4;
    const int bRow = (lane & 7) + ((lane & 16) ? 8 : 0);
    const int bSeg = (lane >> 3) & 1;

    auto prefetch = [&](int c) {
        const int k0 = c * 64;
        const uint32_t base = sb + (uint32_t)(c & 1) * GBUF;
        #pragma unroll
        for (int i = 0; i < 4; i++) {
            int row = lrow + i * 32;
            uint32_t so = swz128((uint32_t)(row * 128 + lseg * 16));
            size_t ga = (size_t)(mBase + row) * DD + k0 + lseg * 8;
            size_t gb = (size_t)(nBase + row) * DD + k0 + lseg * 8;
            cp16(base + so,          Ahi + ga);
            cp16(base + 16384 + so,  Alo + ga);
            cp16(base + 32768 + so,  Bhi + gb);
            cp16(base + 49152 + so,  Blo + gb);
        }
        CP_COMMIT();
    };

    prefetch(0);
    for (int c = 0; c < 16; c++) {
        if (c + 1 < 16) { prefetch(c + 1); CP_WAIT1(); }
        else            { CP_WAIT0(); }
        __syncthreads();

        const uint32_t bA  = sb + (uint32_t)(c & 1) * GBUF;
        const uint32_t bAl = bA + 16384;
        const uint32_t bB  = bA + 32768;
        const uint32_t bBl = bA + 49152;

        #pragma unroll
        for (int ks = 0; ks < 4; ks++) {
            uint32_t ah[4][4], al[4][4], bh[2][4], bl[2][4];
            #pragma unroll
            for (int mt = 0; mt < 4; mt++) {
                uint32_t off = swz128((uint32_t)((warp_m*64 + mt*16 + aRow)*128
                                                  + ks*32 + aSeg*16));
                ldsm_x4(ah[mt][0], ah[mt][1], ah[mt][2], ah[mt][3], bA  + off);
                ldsm_x4(al[mt][0], al[mt][1], al[mt][2], al[mt][3], bAl + off);
            }
            #pragma unroll
            for (int nt2 = 0; nt2 < 2; nt2++) {
                uint32_t off = swz128((uint32_t)((warp_n*32 + nt2*16 + bRow)*128
                                                  + ks*32 + bSeg*16));
                ldsm_x4(bh[nt2][0], bh[nt2][1], bh[nt2][2], bh[nt2][3], bB  + off);
                ldsm_x4(bl[nt2][0], bl[nt2][1], bl[nt2][2], bl[nt2][3], bBl + off);
            }
            #pragma unroll
            for (int mt = 0; mt < 4; mt++) {
                #pragma unroll
                for (int nt = 0; nt < 4; nt++) {
                    uint32_t b0 = (nt < 2) ? bh[0][(nt&1)*2]   : bh[1][(nt&1)*2];
                    uint32_t b1 = (nt < 2) ? bh[0][(nt&1)*2+1] : bh[1][(nt&1)*2+1];
                    uint32_t c0 = (nt < 2) ? bl[0][(nt&1)*2]   : bl[1][(nt&1)*2];
                    uint32_t c1 = (nt < 2) ? bl[0][(nt&1)*2+1] : bl[1][(nt&1)*2+1];
                    mma_bf16(acc[mt][nt], ah[mt][0],ah[mt][1],ah[mt][2],ah[mt][3], b0, b1);
                    mma_bf16(acc[mt][nt], al[mt][0],al[mt][1],al[mt][2],al[mt][3], b0, b1);
                    mma_bf16(acc[mt][nt], ah[mt][0],ah[mt][1],ah[mt][2],ah[mt][3], c0, c1);
                }
            }
        }
        __syncthreads();
    }

    const int rQuad = lane >> 2;
    const int cPair = (lane & 3) * 2;

    #pragma unroll
    for (int mt = 0; mt < 4; mt++) {
        #pragma unroll
        for (int nt = 0; nt < 4; nt++) {
            const int col = nBase + warp_n*32 + nt*8 + cPair;
            #pragma unroll
            for (int hrow = 0; hrow < 2; hrow++) {
                const int row = mBase + warp_m*64 + mt*16 + rQuad + hrow*8;
                float e = acc[mt][nt][hrow*2 + 0];
                float o = acc[mt][nt][hrow*2 + 1];
                if (mode == 0) {
                    *(float2*)(fout + (size_t)row * DD + col) = make_float2(e, o);
                } else {
                    const int b = row >> 11, s = row & 2047;
                    const int h = col >> 6, dk = col & 63;
                    if (mode >= 2) {   // RoPE
                        float cc = g_cos[s*32 + (dk >> 1)];
                        float sn = g_sin[s*32 + (dk >> 1)];
                        float ev = e * cc - o * sn;
                        float od = o * cc + e * sn;
                        e = ev; o = od;
                        if (mode == 2) { e *= 0.125f; o *= 0.125f; }
                    }
                    size_t idx = ((size_t)((b*HH + h)*SS + s)) * DK + dk;
                    if (mode == 1) {
                        // V: write fp16 bits
                        uint32_t hv = pack_h2(e, o);
                        *(uint32_t*)(oh + idx) = hv;
                    } else {
                        __nv_bfloat16 eh = __float2bfloat16(e);
                        __nv_bfloat16 oh2 = __float2bfloat16(o);
                        *(__nv_bfloat162*)(oh + idx) = __nv_bfloat162(eh, oh2);
                    }
                }
            }
        }
    }
}

// ---------------------------------------------------------------------------
// Tensor-core flash attention, causal, cp.async double-buffered K/V.
// 1 CTA = (b,h) x 64 queries; 4 warps x 16 query rows; 64-key tiles.
// QK^T: bf16 (1 pass). PV: fp16 P x fp16 V (1 pass, fp32 accum) — P in [0,1]
// and V ~ N(0,1), fp16 quantization ~2^-12 => output l2 err ~3e-4 < 1e-3.
// Output bf16 hi/lo in [b,s,D].
// smem: Q 8K | buf0 (K 8K | Vf 8K) | buf1 (...)  = 40KB dynamic
// ---------------------------------------------------------------------------
#define FBUF 16384u

__global__ __launch_bounds__(128) void flash_tc_kernel(
    const __nv_bfloat16* __restrict__ Qh, const __nv_bfloat16* __restrict__ Kh,
    const __nv_bfloat16* __restrict__ Vf,
    __nv_bfloat16* __restrict__ Oh, __nv_bfloat16* __restrict__ Ol)
{
    extern __shared__ __align__(1024) char fsm[];
    const uint32_t sQ = smem_u32(fsm);

    const int qb  = gridDim.x - 1 - blockIdx.x;   // big tiles first
    const int bh  = blockIdx.y;
    const int tid = threadIdx.x;
    const int warp = tid >> 5, lane = tid & 31;
    const int quad = lane >> 2, t4 = lane & 3;

    const __nv_bfloat16* Qg  = Qh + ((size_t)bh*SS + qb*64)*DK;
    const __nv_bfloat16* Kg  = Kh + (size_t)bh*SS*DK;
    const __nv_bfloat16* Vfg = Vf + (size_t)bh*SS*DK;

    const int fr = tid >> 1, fs0 = (tid & 1) * 4;

    auto prefetch_kv = [&](int kb) {
        const uint32_t base = sQ + 8192 + (uint32_t)(kb & 1) * FBUF;
        size_t gro = (size_t)(kb*64 + fr) * DK;
        #pragma unroll
        for (int u = 0; u < 4; u++) {
            uint32_t so = swz128((uint32_t)(fr*128 + (fs0+u)*16));
            cp16(base + so,         Kg  + gro + (fs0+u)*8);
            cp16(base + 8192 + so,  Vfg + gro + (fs0+u)*8);
        }
        CP_COMMIT();
    };

    // Load Q tile (64 rows x 128B), swizzled
    {
        #pragma unroll
        for (int u = 0; u < 4; u++) {
            uint32_t so = swz128((uint32_t)(fr*128 + (fs0+u)*16));
            *(uint4*)(fsm + so) = *(const uint4*)(Qg + (size_t)fr*DK + (fs0+u)*8);
        }
    }
    prefetch_kv(0);
    __syncthreads();

    // Hoist Q a-frags
    uint32_t qf[4][4];
    {
        const int aRow = lane & 15, aSeg = lane >> 4;
        #pragma unroll
        for (int ks = 0; ks < 4; ks++) {
            uint32_t off = swz128((uint32_t)((warp*16 + aRow)*128 + ks*32 + aSeg*16));
            ldsm_x4(qf[ks][0], qf[ks][1], qf[ks][2], qf[ks][3], sQ + off);
        }
    }

    float m[2] = {-1e30f, -1e30f}, l[2] = {0.f, 0.f};
    float acc[8][4];
    #pragma unroll
    for (int nt = 0; nt < 8; nt++)
        #pragma unroll
        for (int q = 0; q < 4; q++) acc[nt][q] = 0.f;

    const int bRow = (lane & 7) + ((lane & 16) ? 8 : 0);
    const int bSeg = (lane >> 3) & 1;
    const int vmi = lane >> 3, vrow = lane & 7;

    for (int kb = 0; kb <= qb; kb++) {
        if (kb + 1 <= qb) { prefetch_kv(kb + 1); CP_WAIT1(); }
        else              { CP_WAIT0(); }
        __syncthreads();

        const uint32_t sK = sQ + 8192 + (uint32_t)(kb & 1) * FBUF;
        const uint32_t sV = sK + 8192;

        // S = Q K^T (one bf16 pass)
        float s[8][4];
        #pragma unroll
        for (int nt = 0; nt < 8; nt++)
            #pragma unroll
            for (int q = 0; q < 4; q++) s[nt][q] = 0.f;
        #pragma unroll
        for (int ks = 0; ks < 4; ks++) {
            #pragma unroll
            for (int g = 0; g < 4; g++) {
                uint32_t k0, k1, k2, k3;
                uint32_t off = swz128((uint32_t)((g*16 + bRow)*128 + ks*32 + bSeg*16));
                ldsm_x4(k0, k1, k2, k3, sK + off);
                mma_bf16(s[g*2],   qf[ks][0],qf[ks][1],qf[ks][2],qf[ks][3], k0, k1);
                mma_bf16(s[g*2+1], qf[ks][0],qf[ks][1],qf[ks][2],qf[ks][3], k2, k3);
            }
        }

        if (kb == qb) {   // causal mask on diagonal tile
            #pragma unroll
            for (int nt = 0; nt < 8; nt++)
                #pragma unroll
                for (int e = 0; e < 4; e++) {
                    int qrow = warp*16 + quad + (e >> 1)*8;
                    int kcol = nt*8 + t4*2 + (e & 1);
                    if (kcol > qrow) s[nt][e] = -1e30f;
                }
        }

        // Online softmax
        float corr[2];
        #pragma unroll
        for (int hr = 0; hr < 2; hr++) {
            float mx = -1e30f;
            #pragma unroll
            for (int nt = 0; nt < 8; nt++)
                mx = fmaxf(mx, fmaxf(s[nt][hr*2], s[nt][hr*2+1]));
            mx = fmaxf(mx, __shfl_xor_sync(0xffffffffu, mx, 1));
            mx = fmaxf(mx, __shfl_xor_sync(0xffffffffu, mx, 2));
            float mn = fmaxf(m[hr], mx);
            corr[hr] = __expf(m[hr] - mn);
            m[hr] = mn;
            float sum = 0.f;
            #pragma unroll
            for (int nt = 0; nt < 8; nt++) {
                float p0 = __expf(s[nt][hr*2]   - mn);
                float p1 = __expf(s[nt][hr*2+1] - mn);
                s[nt][hr*2] = p0; s[nt][hr*2+1] = p1;
                sum += p0 + p1;
            }
            sum += __shfl_xor_sync(0xffffffffu, sum, 1);
            sum += __shfl_xor_sync(0xffffffffu, sum, 2);
            l[hr] = l[hr]*corr[hr] + sum;
        }
        #pragma unroll
        for (int nt = 0; nt < 8; nt++) {
            acc[nt][0] *= corr[0]; acc[nt][1] *= corr[0];
            acc[nt][2] *= corr[1]; acc[nt][3] *= corr[1];
        }

        // P -> fp16 fragments (a-frag layout)
        uint32_t ph[8][2];
        #pragma unroll
        for (int nt = 0; nt < 8; nt++) {
            ph[nt][0] = pack_h2(s[nt][0], s[nt][1]);
            ph[nt][1] = pack_h2(s[nt][2], s[nt][3]);
        }

        // O += P * V  (single fp16 pass, fp32 accumulate)
        #pragma unroll
        for (int kt = 0; kt < 4; kt++) {
            uint32_t a0 = ph[2*kt][0],   a1 = ph[2*kt][1];
            uint32_t a2 = ph[2*kt+1][0], a3 = ph[2*kt+1][1];
            #pragma unroll
            for (int g = 0; g < 4; g++) {
                uint32_t off = swz128((uint32_t)(
                    (kt*16 + (vmi & 1)*8 + vrow)*128 + (g*16 + (vmi >> 1)*8)*2));
                uint32_t v0, v1, v2, v3;
                ldsm_x4t(v0, v1, v2, v3, sV + off);
                mma_f16(acc[g*2],   a0, a1, a2, a3, v0, v1);
                mma_f16(acc[g*2+1], a0, a1, a2, a3, v2, v3);
            }
        }
        __syncthreads();
    }

    // Epilogue: O/l, write bf16 hi/lo in [b,s,D]
    const int b = bh >> 4, h = bh & 15;
    #pragma unroll
    for (int hr = 0; hr < 2; hr++) {
        float inv = 1.f / l[hr];
        int srow = qb*64 + warp*16 + quad + hr*8;
        #pragma unroll
        for (int nt = 0; nt < 8; nt++) {
            float e = acc[nt][hr*2]   * inv;
            float o = acc[nt][hr*2+1] * inv;
            __nv_bfloat16 eh = __float2bfloat16(e);
            __nv_bfloat16 oh2 = __float2bfloat16(o);
            __nv_bfloat16 el = __float2bfloat16(e - __bfloat162float(eh));
            __nv_bfloat16 ol2 = __float2bfloat16(o - __bfloat162float(oh2));
            size_t idx = ((size_t)(b*SS + srow))*DD + h*64 + nt*8 + t4*2;
            *(__nv_bfloat162*)(Oh + idx) = __nv_bfloat162(eh, oh2);
            *(__nv_bfloat162*)(Ol + idx) = __nv_bfloat162(el, ol2);
        }
    }
}

// ---------------------------------------------------------------------------
extern "C" void kernel_launch(void* const* d_in, const int* in_sizes, int n_in,
                              void* d_out, int out_size) {
    const float* x  = (const float*)d_in[0];
    const float* wq = (const float*)d_in[1];
    const float* wk = (const float*)d_in[2];
    const float* wv = (const float*)d_in[3];
    const float* wo = (const float*)d_in[4];
    float* out = (float*)d_out;

    __nv_bfloat16 *pqh, *pkh, *pvf, *pxh, *pxl, *pwh, *pwl, *pah, *pal;
    cudaGetSymbolAddress((void**)&pqh, g_qh);
    cudaGetSymbolAddress((void**)&pkh, g_kh);
    cudaGetSymbolAddress((void**)&pvf, g_vf);
    cudaGetSymbolAddress((void**)&pxh, g_xhi);
    cudaGetSymbolAddress((void**)&pxl, g_xlo);
    cudaGetSymbolAddress((void**)&pwh, g_whi);
    cudaGetSymbolAddress((void**)&pwl, g_wlo);
    cudaGetSymbolAddress((void**)&pah, g_ahi);
    cudaGetSymbolAddress((void**)&pal, g_alo);

    cudaFuncSetAttribute(tcgemm_kernel,
                         cudaFuncAttributeMaxDynamicSharedMemorySize, 2*GBUF);
    cudaFuncSetAttribute(flash_tc_kernel,
                         cudaFuncAttributeMaxDynamicSharedMemorySize, 8192 + 2*FBUF);

    rope_table_kernel<<<64, 1024>>>();

    // One fused split: x (4096 blocks) + 4 weights (4 x 1024 blocks)
    split_all_kernel<<<8192, 256>>>(x, wq, wk, wv, wo);

    // Fused Q/K/V projection: grid.z selects weight + epilogue
    dim3 qkvGrid(8, 32, 3);
    tcgemm_kernel<<<qkvGrid, 256, 2*GBUF>>>(pxh, pxl, pwh, pwl,
                                            nullptr, nullptr, nullptr, 9);

    flash_tc_kernel<<<dim3(32, 32), 128, 8192 + 2*FBUF>>>(pqh, pkh, pvf,
                                                          pah, pal);

    const size_t nw = (size_t)DD * DD;
    dim3 gGrid(8, 32);
    tcgemm_kernel<<<gGrid, 256, 2*GBUF>>>(pah, pal, pwh + 3*nw, pwl + 3*nw,
                                          out, nullptr, nullptr, 0);   // out proj
}